// round 5
// baseline (speedup 1.0000x reference)
#include <cuda_runtime.h>
#include <cuda_bf16.h>
#include <cstdint>

// Problem constants
#define B_   4
#define T_   2048
#define C_   1024
#define H_   16
#define DH_  64
#define M_   (B_ * T_)          // 8192
#define N_QKV (3 * C_)          // 3072
#define K_   1024

// ---------------------------------------------------------------------------
// Device-global scratch (allocation-free rule)
// ---------------------------------------------------------------------------
__device__ __nv_bfloat16 g_qh[B_ * H_ * T_ * DH_];
__device__ __nv_bfloat16 g_ql[B_ * H_ * T_ * DH_];
__device__ __nv_bfloat16 g_kh[B_ * H_ * T_ * DH_];
__device__ __nv_bfloat16 g_kl[B_ * H_ * T_ * DH_];
__device__ __nv_bfloat16 g_vh[B_ * H_ * T_ * DH_];
__device__ __nv_bfloat16 g_vl[B_ * H_ * T_ * DH_];
__device__ __nv_bfloat16 g_xh[M_ * K_];
__device__ __nv_bfloat16 g_xl[M_ * K_];
__device__ __nv_bfloat16 g_yh[M_ * C_];
__device__ __nv_bfloat16 g_yl[M_ * C_];
__device__ __nv_bfloat16 g_wqkvTh[N_QKV * K_];   // [N][K]
__device__ __nv_bfloat16 g_wqkvTl[N_QKV * K_];
__device__ __nv_bfloat16 g_wprojTh[C_ * K_];
__device__ __nv_bfloat16 g_wprojTl[C_ * K_];

#define SMEM_SWIZZLE_128B(o) ((o) ^ (((o) >> 3) & 0x70))

__device__ __forceinline__ uint32_t smem_to_u32(const void* p) {
    uint32_t a;
    asm("{ .reg .u64 t; cvta.to.shared.u64 t, %1; cvt.u32.u64 %0, t; }" : "=r"(a) : "l"(p));
    return a;
}
__device__ __forceinline__ void cp16(uint32_t saddr, const void* g) {
    asm volatile("cp.async.cg.shared.global [%0], [%1], 16;" :: "r"(saddr), "l"(g));
}
__device__ __forceinline__ void cp_commit() {
    asm volatile("cp.async.commit_group;" ::: "memory");
}
__device__ __forceinline__ void ldsm_x4(uint32_t* r, uint32_t addr) {
    asm volatile("ldmatrix.sync.aligned.m8n8.x4.shared.b16 {%0,%1,%2,%3}, [%4];"
        : "=r"(r[0]), "=r"(r[1]), "=r"(r[2]), "=r"(r[3]) : "r"(addr));
}
__device__ __forceinline__ void ldsm_x2(uint32_t* r, uint32_t addr) {
    asm volatile("ldmatrix.sync.aligned.m8n8.x2.shared.b16 {%0,%1}, [%2];"
        : "=r"(r[0]), "=r"(r[1]) : "r"(addr));
}
__device__ __forceinline__ void ldsm_x2_trans(uint32_t* r, uint32_t addr) {
    asm volatile("ldmatrix.sync.aligned.m8n8.x2.trans.shared.b16 {%0,%1}, [%2];"
        : "=r"(r[0]), "=r"(r[1]) : "r"(addr));
}
__device__ __forceinline__ void mma_bf16(float* c, const uint32_t* a, const uint32_t* b) {
    asm volatile("mma.sync.aligned.m16n8k16.row.col.f32.bf16.bf16.f32 "
        "{%0,%1,%2,%3}, {%4,%5,%6,%7}, {%8,%9}, {%0,%1,%2,%3};"
        : "+f"(c[0]), "+f"(c[1]), "+f"(c[2]), "+f"(c[3])
        : "r"(a[0]), "r"(a[1]), "r"(a[2]), "r"(a[3]), "r"(b[0]), "r"(b[1]));
}
__device__ __forceinline__ uint32_t cvt_bf16x2(float hi, float lo) {
    uint32_t d;
    asm("cvt.rn.bf16x2.f32 %0, %1, %2;" : "=r"(d) : "f"(hi), "f"(lo));
    return d;
}

// ---------------------------------------------------------------------------
// Prep: split x (fp32) into bf16 hi/lo
// ---------------------------------------------------------------------------
__global__ __launch_bounds__(256) void convert_x_kernel(const float* __restrict__ x)
{
    int idx = (blockIdx.x * 256 + threadIdx.x) * 4;
    float4 v = *(const float4*)(x + idx);
    __nv_bfloat16 h[4], l[4];
    float vv[4] = {v.x, v.y, v.z, v.w};
#pragma unroll
    for (int i = 0; i < 4; i++) {
        h[i] = __float2bfloat16(vv[i]);
        l[i] = __float2bfloat16(vv[i] - __bfloat162float(h[i]));
    }
    *(uint2*)(g_xh + idx) = *(uint2*)h;
    *(uint2*)(g_xl + idx) = *(uint2*)l;
}

// ---------------------------------------------------------------------------
// Prep: transpose W [K,N] -> WT hi/lo [N,K] bf16
// ---------------------------------------------------------------------------
__global__ __launch_bounds__(256) void transpose_w_kernel(
    const float* __restrict__ W, __nv_bfloat16* __restrict__ WTh,
    __nv_bfloat16* __restrict__ WTl, int N)
{
    __shared__ float t[32][33];
    int n0 = blockIdx.x * 32, k0 = blockIdx.y * 32;
    int tx = threadIdx.x, ty = threadIdx.y;
#pragma unroll
    for (int i = 0; i < 4; i++)
        t[ty + i * 8][tx] = W[(size_t)(k0 + ty + i * 8) * N + n0 + tx];
    __syncthreads();
#pragma unroll
    for (int i = 0; i < 4; i++) {
        int n = n0 + ty + i * 8;
        int k = k0 + tx;
        float v = t[tx][ty + i * 8];
        __nv_bfloat16 h = __float2bfloat16(v);
        __nv_bfloat16 l = __float2bfloat16(v - __bfloat162float(h));
        WTh[(size_t)n * K_ + k] = h;
        WTl[(size_t)n * K_ + k] = l;
    }
}

// ---------------------------------------------------------------------------
// Tensor-core GEMM (3-term hi/lo split). C[M,N] = A[M,K] @ B[N,K]^T.
// 128x128 CTA tile, BK=64, 512 threads / 16 warps (4x4), warp tile 32x32.
// cp.async double-buffered. mode 0: split-scatter to q/k/v; mode 1: f32 store.
// ---------------------------------------------------------------------------
#define STAGE_BYTES 65536
#define SM_GEMM_TOTAL (2 * STAGE_BYTES)

__global__ __launch_bounds__(512) void mma_gemm_kernel(
    const __nv_bfloat16* __restrict__ Ah, const __nv_bfloat16* __restrict__ Al,
    const __nv_bfloat16* __restrict__ Bh, const __nv_bfloat16* __restrict__ Bl,
    float* __restrict__ out, int mode)
{
    extern __shared__ char smem[];
    uint32_t sbase = smem_to_u32(smem);

    int tid = threadIdx.x;
    int wid = tid >> 5;
    int lane = tid & 31;
    int wm = wid >> 2;          // 0..3 (m)
    int wn = wid & 3;           // 0..3 (n)

    int m0 = blockIdx.y * 128;
    int n0 = blockIdx.x * 128;

    float acc[2][4][4];
#pragma unroll
    for (int i = 0; i < 2; i++)
#pragma unroll
        for (int j = 0; j < 4; j++)
#pragma unroll
            for (int c = 0; c < 4; c++) acc[i][j][c] = 0.f;

    auto load_chunk = [&](int kt, int s) {
        uint32_t st = sbase + s * STAGE_BYTES;
#pragma unroll
        for (int p = 0; p < 2; p++) {
            int idx = tid + p * 512;       // 0..1023
            int row = idx >> 3;
            int ch  = idx & 7;
            uint32_t so = SMEM_SWIZZLE_128B(row * 128 + ch * 16);
            size_t ka = (size_t)(m0 + row) * K_ + kt * 64 + ch * 8;
            size_t kb = (size_t)(n0 + row) * K_ + kt * 64 + ch * 8;
            cp16(st + so,         Ah + ka);
            cp16(st + 16384 + so, Al + ka);
            cp16(st + 32768 + so, Bh + kb);
            cp16(st + 49152 + so, Bl + kb);
        }
        cp_commit();
    };

    load_chunk(0, 0);

    int a_row = lane & 15;
    int a_cb  = (lane >> 4) << 4;
    int b_row = lane & 7;
    int b_cb  = ((lane >> 3) & 1) << 4;

    for (int kt = 0; kt < 16; kt++) {
        int s = kt & 1;
        if (kt + 1 < 16) {
            load_chunk(kt + 1, (kt + 1) & 1);
            asm volatile("cp.async.wait_group 1;" ::: "memory");
        } else {
            asm volatile("cp.async.wait_group 0;" ::: "memory");
        }
        __syncthreads();

        uint32_t sAh = sbase + s * STAGE_BYTES;
        uint32_t sAl = sAh + 16384;
        uint32_t sBh = sAh + 32768;
        uint32_t sBl = sAh + 49152;

#pragma unroll
        for (int ks = 0; ks < 4; ks++) {
            int kB = ks * 32;
            uint32_t ah[2][4], al[2][4], bh[4][2], bl[4][2];
#pragma unroll
            for (int i = 0; i < 2; i++) {
                uint32_t off = SMEM_SWIZZLE_128B((wm * 32 + i * 16 + a_row) * 128 + kB + a_cb);
                ldsm_x4(ah[i], sAh + off);
                ldsm_x4(al[i], sAl + off);
            }
#pragma unroll
            for (int j = 0; j < 4; j++) {
                uint32_t off = SMEM_SWIZZLE_128B((wn * 32 + j * 8 + b_row) * 128 + kB + b_cb);
                ldsm_x2(bh[j], sBh + off);
                ldsm_x2(bl[j], sBl + off);
            }
#pragma unroll
            for (int i = 0; i < 2; i++)
#pragma unroll
                for (int j = 0; j < 4; j++) mma_bf16(acc[i][j], ah[i], bh[j]);
#pragma unroll
            for (int i = 0; i < 2; i++)
#pragma unroll
                for (int j = 0; j < 4; j++) mma_bf16(acc[i][j], ah[i], bl[j]);
#pragma unroll
            for (int i = 0; i < 2; i++)
#pragma unroll
                for (int j = 0; j < 4; j++) mma_bf16(acc[i][j], al[i], bh[j]);
        }
        __syncthreads();
    }

    int r4 = lane >> 2;
    int cp2 = (lane & 3) * 2;

    if (mode == 1) {
#pragma unroll
        for (int i = 0; i < 2; i++)
#pragma unroll
            for (int j = 0; j < 4; j++) {
                int n = n0 + wn * 32 + j * 8 + cp2;
#pragma unroll
                for (int rr = 0; rr < 2; rr++) {
                    int m = m0 + wm * 32 + i * 16 + r4 + rr * 8;
                    *(float2*)(out + (size_t)m * C_ + n) =
                        make_float2(acc[i][j][rr * 2], acc[i][j][rr * 2 + 1]);
                }
            }
    } else {
        int which = n0 >> 10;
        __nv_bfloat16* dh = (which == 0) ? g_qh : (which == 1) ? g_kh : g_vh;
        __nv_bfloat16* dl = (which == 0) ? g_ql : (which == 1) ? g_kl : g_vl;
        float scale = (which == 0) ? 0.125f : 1.0f;
#pragma unroll
        for (int i = 0; i < 2; i++)
#pragma unroll
            for (int j = 0; j < 4; j++) {
                int n = n0 + wn * 32 + j * 8 + cp2;
                int h = (n & 1023) >> 6;
                int d = n & 63;
#pragma unroll
                for (int rr = 0; rr < 2; rr++) {
                    int m = m0 + wm * 32 + i * 16 + r4 + rr * 8;
                    int b = m >> 11;
                    int t = m & 2047;
                    size_t off = (size_t)(((b << 4) + h) * T_ + t) * DH_ + d;
                    float v0 = acc[i][j][rr * 2] * scale;
                    float v1 = acc[i][j][rr * 2 + 1] * scale;
                    __nv_bfloat16 h0 = __float2bfloat16(v0);
                    __nv_bfloat16 h1 = __float2bfloat16(v1);
                    float l0 = v0 - __bfloat162float(h0);
                    float l1 = v1 - __bfloat162float(h1);
                    uint16_t u0, u1;
                    memcpy(&u0, &h0, 2); memcpy(&u1, &h1, 2);
                    *(uint32_t*)(dh + off) = (uint32_t)u0 | ((uint32_t)u1 << 16);
                    *(uint32_t*)(dl + off) = cvt_bf16x2(l1, l0);
                }
            }
    }
}

// ---------------------------------------------------------------------------
// Tensor-core causal flash attention (unchanged structure).
// ---------------------------------------------------------------------------
#define AS_QH 0
#define AS_QL 16384
#define AS_KV 32768
#define AS_TOTAL (32768 + 2 * 32768)   // 98304

__global__ __launch_bounds__(256) void attn_mma_kernel()
{
    extern __shared__ char smem[];
    uint32_t sb = smem_to_u32(smem);
    int tid = threadIdx.x;
    int wid = tid >> 5;
    int lane = tid & 31;

    int qt = blockIdx.x;
    int bh = blockIdx.y;
    int q0 = qt * 128;
    size_t base = (size_t)bh * T_ * DH_;
    int nkt = 2 * qt + 2;

#pragma unroll
    for (int p = 0; p < 4; p++) {
        int idx = tid + p * 256;
        int row = idx >> 3;
        int ch  = idx & 7;
        uint32_t so = SMEM_SWIZZLE_128B(row * 128 + ch * 16);
        size_t g = base + (size_t)(q0 + row) * DH_ + ch * 8;
        cp16(sb + AS_QH + so, g_qh + g);
        cp16(sb + AS_QL + so, g_ql + g);
    }
    cp_commit();

    auto load_kv = [&](int j, int s) {
        uint32_t st = sb + AS_KV + s * 32768;
#pragma unroll
        for (int p = 0; p < 2; p++) {
            int idx = tid + p * 256;
            int row = idx >> 3;
            int ch  = idx & 7;
            uint32_t so = SMEM_SWIZZLE_128B(row * 128 + ch * 16);
            size_t g = base + (size_t)(j * 64 + row) * DH_ + ch * 8;
            cp16(st + so,         g_kh + g);
            cp16(st + 8192 + so,  g_kl + g);
            cp16(st + 16384 + so, g_vh + g);
            cp16(st + 24576 + so, g_vl + g);
        }
        cp_commit();
    };

    load_kv(0, 0);

    uint32_t qh[4][4], ql[4][4];
    float O[8][4];
#pragma unroll
    for (int dt = 0; dt < 8; dt++)
#pragma unroll
        for (int c = 0; c < 4; c++) O[dt][c] = 0.f;
    float m0r = -1e30f, m1r = -1e30f, l0r = 0.f, l1r = 0.f;

    int g4 = lane >> 2;
    int c2 = 2 * (lane & 3);
    int a_row = lane & 15;
    int a_cb  = (lane >> 4) << 4;
    int b_row = lane & 7;
    int b_cb  = ((lane >> 3) & 1) << 4;
    int v_row = (lane & 7) + ((lane >> 3) & 1) * 8;

    for (int j = 0; j < nkt; j++) {
        int s = j & 1;
        if (j + 1 < nkt) {
            load_kv(j + 1, (j + 1) & 1);
            asm volatile("cp.async.wait_group 1;" ::: "memory");
        } else {
            asm volatile("cp.async.wait_group 0;" ::: "memory");
        }
        __syncthreads();

        if (j == 0) {
#pragma unroll
            for (int ks = 0; ks < 4; ks++) {
                uint32_t off = SMEM_SWIZZLE_128B((wid * 16 + a_row) * 128 + ks * 32 + a_cb);
                ldsm_x4(qh[ks], sb + AS_QH + off);
                ldsm_x4(ql[ks], sb + AS_QL + off);
            }
        }

        uint32_t stK = sb + AS_KV + s * 32768;
        uint32_t stV = stK + 16384;

        float S[8][4];
#pragma unroll
        for (int jt = 0; jt < 8; jt++) {
#pragma unroll
            for (int c = 0; c < 4; c++) S[jt][c] = 0.f;
#pragma unroll
            for (int ks = 0; ks < 4; ks++) {
                uint32_t off = SMEM_SWIZZLE_128B((jt * 8 + b_row) * 128 + ks * 32 + b_cb);
                uint32_t kh[2], kl[2];
                ldsm_x2(kh, stK + off);
                ldsm_x2(kl, stK + 8192 + off);
                mma_bf16(S[jt], qh[ks], kh);
                mma_bf16(S[jt], qh[ks], kl);
                mma_bf16(S[jt], ql[ks], kh);
            }
        }

        if (j >= 2 * qt) {
            int r0 = q0 + wid * 16 + g4;
            int cb = j * 64 + c2;
#pragma unroll
            for (int jt = 0; jt < 8; jt++) {
                int c0 = cb + jt * 8;
                if (c0 > r0)     S[jt][0] = -1e30f;
                if (c0 + 1 > r0) S[jt][1] = -1e30f;
                if (c0 > r0 + 8)     S[jt][2] = -1e30f;
                if (c0 + 1 > r0 + 8) S[jt][3] = -1e30f;
            }
        }

        float mx0 = -1e30f, mx1 = -1e30f;
#pragma unroll
        for (int jt = 0; jt < 8; jt++) {
            mx0 = fmaxf(mx0, fmaxf(S[jt][0], S[jt][1]));
            mx1 = fmaxf(mx1, fmaxf(S[jt][2], S[jt][3]));
        }
        mx0 = fmaxf(mx0, __shfl_xor_sync(0xffffffffu, mx0, 1));
        mx0 = fmaxf(mx0, __shfl_xor_sync(0xffffffffu, mx0, 2));
        mx1 = fmaxf(mx1, __shfl_xor_sync(0xffffffffu, mx1, 1));
        mx1 = fmaxf(mx1, __shfl_xor_sync(0xffffffffu, mx1, 2));

        float mn0 = fmaxf(m0r, mx0), mn1 = fmaxf(m1r, mx1);
        float al0 = __expf(m0r - mn0), al1 = __expf(m1r - mn1);
        m0r = mn0; m1r = mn1;

        float s0 = 0.f, s1 = 0.f;
#pragma unroll
        for (int jt = 0; jt < 8; jt++) {
            S[jt][0] = __expf(S[jt][0] - mn0); s0 += S[jt][0];
            S[jt][1] = __expf(S[jt][1] - mn0); s0 += S[jt][1];
            S[jt][2] = __expf(S[jt][2] - mn1); s1 += S[jt][2];
            S[jt][3] = __expf(S[jt][3] - mn1); s1 += S[jt][3];
        }
        s0 += __shfl_xor_sync(0xffffffffu, s0, 1);
        s0 += __shfl_xor_sync(0xffffffffu, s0, 2);
        s1 += __shfl_xor_sync(0xffffffffu, s1, 1);
        s1 += __shfl_xor_sync(0xffffffffu, s1, 2);
        l0r = l0r * al0 + s0;
        l1r = l1r * al1 + s1;

#pragma unroll
        for (int dt = 0; dt < 8; dt++) {
            O[dt][0] *= al0; O[dt][1] *= al0;
            O[dt][2] *= al1; O[dt][3] *= al1;
        }

        uint32_t aPh[4][4], aPl[4][4];
#pragma unroll
        for (int ks2 = 0; ks2 < 4; ks2++) {
#pragma unroll
            for (int q = 0; q < 4; q++) {
                int tile = 2 * ks2 + (q >> 1);
                int cb = (q & 1) * 2;
                float p0 = S[tile][cb], p1 = S[tile][cb + 1];
                uint32_t t0 = __float_as_uint(p0) & 0xFFFF0000u;
                uint32_t t1 = __float_as_uint(p1) & 0xFFFF0000u;
                aPh[ks2][q] = (t0 >> 16) | t1;
                aPl[ks2][q] = cvt_bf16x2(p1 - __uint_as_float(t1),
                                         p0 - __uint_as_float(t0));
            }
        }

#pragma unroll
        for (int dt = 0; dt < 8; dt++) {
#pragma unroll
            for (int ks2 = 0; ks2 < 4; ks2++) {
                uint32_t off = SMEM_SWIZZLE_128B((ks2 * 16 + v_row) * 128 + dt * 16);
                uint32_t vh[2], vl[2];
                ldsm_x2_trans(vh, stV + off);
                ldsm_x2_trans(vl, stV + 8192 + off);
                mma_bf16(O[dt], aPh[ks2], vh);
                mma_bf16(O[dt], aPh[ks2], vl);
                mma_bf16(O[dt], aPl[ks2], vh);
            }
        }
        __syncthreads();
    }

    float li0 = 1.f / l0r, li1 = 1.f / l1r;
    int b = bh >> 4, h = bh & 15;
    int r0 = q0 + wid * 16 + g4;
#pragma unroll
    for (int dt = 0; dt < 8; dt++) {
        int d = dt * 8 + c2;
        {
            float v0 = O[dt][0] * li0, v1 = O[dt][1] * li0;
            size_t off = (size_t)(b * T_ + r0) * C_ + h * DH_ + d;
            __nv_bfloat16 h0 = __float2bfloat16(v0), h1 = __float2bfloat16(v1);
            float lo0 = v0 - __bfloat162float(h0), lo1 = v1 - __bfloat162float(h1);
            uint16_t u0, u1; memcpy(&u0, &h0, 2); memcpy(&u1, &h1, 2);
            *(uint32_t*)(g_yh + off) = (uint32_t)u0 | ((uint32_t)u1 << 16);
            *(uint32_t*)(g_yl + off) = cvt_bf16x2(lo1, lo0);
        }
        {
            float v0 = O[dt][2] * li1, v1 = O[dt][3] * li1;
            size_t off = (size_t)(b * T_ + r0 + 8) * C_ + h * DH_ + d;
            __nv_bfloat16 h0 = __float2bfloat16(v0), h1 = __float2bfloat16(v1);
            float lo0 = v0 - __bfloat162float(h0), lo1 = v1 - __bfloat162float(h1);
            uint16_t u0, u1; memcpy(&u0, &h0, 2); memcpy(&u1, &h1, 2);
            *(uint32_t*)(g_yh + off) = (uint32_t)u0 | ((uint32_t)u1 << 16);
            *(uint32_t*)(g_yl + off) = cvt_bf16x2(lo1, lo0);
        }
    }
}

// ---------------------------------------------------------------------------
extern "C" void kernel_launch(void* const* d_in, const int* in_sizes, int n_in,
                              void* d_out, int out_size)
{
    const float* x      = (const float*)d_in[0];
    const float* w_qkv  = (const float*)d_in[1];
    const float* w_proj = (const float*)d_in[2];
    float* out = (float*)d_out;
    (void)in_sizes; (void)n_in; (void)out_size;

    cudaFuncSetAttribute(mma_gemm_kernel,
                         cudaFuncAttributeMaxDynamicSharedMemorySize, SM_GEMM_TOTAL);
    cudaFuncSetAttribute(attn_mma_kernel,
                         cudaFuncAttributeMaxDynamicSharedMemorySize, AS_TOTAL);

    __nv_bfloat16 *xh, *xl, *yh, *yl, *wqh, *wql, *wph, *wpl;
    cudaGetSymbolAddress((void**)&xh,  g_xh);
    cudaGetSymbolAddress((void**)&xl,  g_xl);
    cudaGetSymbolAddress((void**)&yh,  g_yh);
    cudaGetSymbolAddress((void**)&yl,  g_yl);
    cudaGetSymbolAddress((void**)&wqh, g_wqkvTh);
    cudaGetSymbolAddress((void**)&wql, g_wqkvTl);
    cudaGetSymbolAddress((void**)&wph, g_wprojTh);
    cudaGetSymbolAddress((void**)&wpl, g_wprojTl);

    // prep
    convert_x_kernel<<<M_ * K_ / (256 * 4), 256>>>(x);
    transpose_w_kernel<<<dim3(N_QKV / 32, K_ / 32), dim3(32, 8)>>>(w_qkv, wqh, wql, N_QKV);
    transpose_w_kernel<<<dim3(C_ / 32, K_ / 32), dim3(32, 8)>>>(w_proj, wph, wpl, C_);

    // QKV GEMM with fused hi/lo split-scatter + q scale
    mma_gemm_kernel<<<dim3(N_QKV / 128, M_ / 128), 512, SM_GEMM_TOTAL>>>(
        xh, xl, wqh, wql, nullptr, 0);

    // tensor-core causal flash attention
    attn_mma_kernel<<<dim3(T_ / 128, B_ * H_), 256, AS_TOTAL>>>();

    // output projection GEMM
    mma_gemm_kernel<<<dim3(C_ / 128, M_ / 128), 512, SM_GEMM_TOTAL>>>(
        yh, yl, wph, wpl, out, 1);
}

// round 6
// speedup vs baseline: 1.0237x; 1.0237x over previous
#include <cuda_runtime.h>
#include <cuda_bf16.h>
#include <cstdint>

// Problem constants
#define B_   4
#define T_   2048
#define C_   1024
#define H_   16
#define DH_  64
#define M_   (B_ * T_)          // 8192
#define N_QKV (3 * C_)          // 3072
#define K_   1024

// ---------------------------------------------------------------------------
// Device-global scratch (allocation-free rule)
// ---------------------------------------------------------------------------
__device__ __nv_bfloat16 g_qh[B_ * H_ * T_ * DH_];
__device__ __nv_bfloat16 g_ql[B_ * H_ * T_ * DH_];
__device__ __nv_bfloat16 g_kh[B_ * H_ * T_ * DH_];
__device__ __nv_bfloat16 g_kl[B_ * H_ * T_ * DH_];
__device__ __nv_bfloat16 g_vh[B_ * H_ * T_ * DH_];
__device__ __nv_bfloat16 g_vl[B_ * H_ * T_ * DH_];
__device__ __nv_bfloat16 g_xh[M_ * K_];
__device__ __nv_bfloat16 g_xl[M_ * K_];
__device__ __nv_bfloat16 g_yh[M_ * C_];
__device__ __nv_bfloat16 g_yl[M_ * C_];
__device__ __nv_bfloat16 g_wqkvTh[N_QKV * K_];   // [N][K]
__device__ __nv_bfloat16 g_wqkvTl[N_QKV * K_];
__device__ __nv_bfloat16 g_wprojTh[C_ * K_];
__device__ __nv_bfloat16 g_wprojTl[C_ * K_];

#define SMEM_SWIZZLE_128B(o) ((o) ^ (((o) >> 3) & 0x70))

__device__ __forceinline__ uint32_t smem_to_u32(const void* p) {
    uint32_t a;
    asm("{ .reg .u64 t; cvta.to.shared.u64 t, %1; cvt.u32.u64 %0, t; }" : "=r"(a) : "l"(p));
    return a;
}
__device__ __forceinline__ void cp16(uint32_t saddr, const void* g) {
    asm volatile("cp.async.cg.shared.global [%0], [%1], 16;" :: "r"(saddr), "l"(g));
}
__device__ __forceinline__ void cp_commit() {
    asm volatile("cp.async.commit_group;" ::: "memory");
}
__device__ __forceinline__ void ldsm_x4(uint32_t* r, uint32_t addr) {
    asm volatile("ldmatrix.sync.aligned.m8n8.x4.shared.b16 {%0,%1,%2,%3}, [%4];"
        : "=r"(r[0]), "=r"(r[1]), "=r"(r[2]), "=r"(r[3]) : "r"(addr));
}
__device__ __forceinline__ void ldsm_x2(uint32_t* r, uint32_t addr) {
    asm volatile("ldmatrix.sync.aligned.m8n8.x2.shared.b16 {%0,%1}, [%2];"
        : "=r"(r[0]), "=r"(r[1]) : "r"(addr));
}
__device__ __forceinline__ void ldsm_x2_trans(uint32_t* r, uint32_t addr) {
    asm volatile("ldmatrix.sync.aligned.m8n8.x2.trans.shared.b16 {%0,%1}, [%2];"
        : "=r"(r[0]), "=r"(r[1]) : "r"(addr));
}
__device__ __forceinline__ void mma_bf16(float* c, const uint32_t* a, const uint32_t* b) {
    asm volatile("mma.sync.aligned.m16n8k16.row.col.f32.bf16.bf16.f32 "
        "{%0,%1,%2,%3}, {%4,%5,%6,%7}, {%8,%9}, {%0,%1,%2,%3};"
        : "+f"(c[0]), "+f"(c[1]), "+f"(c[2]), "+f"(c[3])
        : "r"(a[0]), "r"(a[1]), "r"(a[2]), "r"(a[3]), "r"(b[0]), "r"(b[1]));
}
__device__ __forceinline__ uint32_t cvt_bf16x2(float hi, float lo) {
    uint32_t d;
    asm("cvt.rn.bf16x2.f32 %0, %1, %2;" : "=r"(d) : "f"(hi), "f"(lo));
    return d;
}

// ---------------------------------------------------------------------------
// Prep: split x (fp32) into bf16 hi/lo
// ---------------------------------------------------------------------------
__global__ __launch_bounds__(256) void convert_x_kernel(const float* __restrict__ x)
{
    int idx = (blockIdx.x * 256 + threadIdx.x) * 4;
    float4 v = *(const float4*)(x + idx);
    __nv_bfloat16 h[4], l[4];
    float vv[4] = {v.x, v.y, v.z, v.w};
#pragma unroll
    for (int i = 0; i < 4; i++) {
        h[i] = __float2bfloat16(vv[i]);
        l[i] = __float2bfloat16(vv[i] - __bfloat162float(h[i]));
    }
    *(uint2*)(g_xh + idx) = *(uint2*)h;
    *(uint2*)(g_xl + idx) = *(uint2*)l;
}

// ---------------------------------------------------------------------------
// Prep: transpose W [K,N] -> WT hi/lo [N,K] bf16
// ---------------------------------------------------------------------------
__global__ __launch_bounds__(256) void transpose_w_kernel(
    const float* __restrict__ W, __nv_bfloat16* __restrict__ WTh,
    __nv_bfloat16* __restrict__ WTl, int N)
{
    __shared__ float t[32][33];
    int n0 = blockIdx.x * 32, k0 = blockIdx.y * 32;
    int tx = threadIdx.x, ty = threadIdx.y;
#pragma unroll
    for (int i = 0; i < 4; i++)
        t[ty + i * 8][tx] = W[(size_t)(k0 + ty + i * 8) * N + n0 + tx];
    __syncthreads();
#pragma unroll
    for (int i = 0; i < 4; i++) {
        int n = n0 + ty + i * 8;
        int k = k0 + tx;
        float v = t[tx][ty + i * 8];
        __nv_bfloat16 h = __float2bfloat16(v);
        __nv_bfloat16 l = __float2bfloat16(v - __bfloat162float(h));
        WTh[(size_t)n * K_ + k] = h;
        WTl[(size_t)n * K_ + k] = l;
    }
}

// ---------------------------------------------------------------------------
// Tensor-core GEMM (3-term hi/lo split). C[M,N] = A[M,K] @ B[N,K]^T.
// 128x128 CTA tile, BK=64, 256 threads / 8 warps (2x4), warp tile 64x32.
// 3-stage cp.async ring (192KB smem). B frags via paired ldsm_x4.
// mode 0: split-scatter to q/k/v; mode 1: f32 store.
// ---------------------------------------------------------------------------
#define STAGE_BYTES 65536
#define SM_GEMM_TOTAL (3 * STAGE_BYTES)   // 196608

__global__ __launch_bounds__(256) void mma_gemm_kernel(
    const __nv_bfloat16* __restrict__ Ah, const __nv_bfloat16* __restrict__ Al,
    const __nv_bfloat16* __restrict__ Bh, const __nv_bfloat16* __restrict__ Bl,
    float* __restrict__ out, int mode)
{
    extern __shared__ char smem[];
    uint32_t sbase = smem_to_u32(smem);

    int tid = threadIdx.x;
    int wid = tid >> 5;
    int lane = tid & 31;
    int wm = wid >> 2;          // 0..1 (m)
    int wn = wid & 3;           // 0..3 (n)

    int m0 = blockIdx.y * 128;
    int n0 = blockIdx.x * 128;

    float acc[4][4][4];
#pragma unroll
    for (int i = 0; i < 4; i++)
#pragma unroll
        for (int j = 0; j < 4; j++)
#pragma unroll
            for (int c = 0; c < 4; c++) acc[i][j][c] = 0.f;

    auto load_chunk = [&](int kt, int s) {
        uint32_t st = sbase + s * STAGE_BYTES;
#pragma unroll
        for (int p = 0; p < 4; p++) {
            int idx = tid + p * 256;
            int row = idx >> 3;
            int ch  = idx & 7;
            uint32_t so = SMEM_SWIZZLE_128B(row * 128 + ch * 16);
            size_t ka = (size_t)(m0 + row) * K_ + kt * 64 + ch * 8;
            size_t kb = (size_t)(n0 + row) * K_ + kt * 64 + ch * 8;
            cp16(st + so,         Ah + ka);
            cp16(st + 16384 + so, Al + ka);
            cp16(st + 32768 + so, Bh + kb);
            cp16(st + 49152 + so, Bl + kb);
        }
        cp_commit();
    };

    load_chunk(0, 0);
    load_chunk(1, 1);

    int a_row = lane & 15;
    int a_cb  = (lane >> 4) << 4;
    // paired-B ldsm_x4 addressing: lanes 0-7 -> (jt, klo), 8-15 -> (jt, khi),
    // 16-23 -> (jt+1, klo), 24-31 -> (jt+1, khi)
    int bg      = lane >> 3;              // 0..3
    int bp_row  = (lane & 7) + ((bg >> 1) << 3);   // + 8 rows for second tile
    int bp_cb   = (bg & 1) << 4;

    for (int kt = 0; kt < 16; kt++) {
        int s = kt % 3;
        if (kt + 2 < 16) {
            load_chunk(kt + 2, (kt + 2) % 3);
            asm volatile("cp.async.wait_group 2;" ::: "memory");
        } else if (kt + 1 < 16) {
            asm volatile("cp.async.wait_group 1;" ::: "memory");
        } else {
            asm volatile("cp.async.wait_group 0;" ::: "memory");
        }
        __syncthreads();

        uint32_t sAh = sbase + s * STAGE_BYTES;
        uint32_t sAl = sAh + 16384;
        uint32_t sBh = sAh + 32768;
        uint32_t sBl = sAh + 49152;

#pragma unroll
        for (int ks = 0; ks < 4; ks++) {
            int kB = ks * 32;
            uint32_t ah[4][4], al[4][4], bh[4][2], bl[4][2];
#pragma unroll
            for (int i = 0; i < 4; i++) {
                uint32_t off = SMEM_SWIZZLE_128B((wm * 64 + i * 16 + a_row) * 128 + kB + a_cb);
                ldsm_x4(ah[i], sAh + off);
                ldsm_x4(al[i], sAl + off);
            }
#pragma unroll
            for (int jp = 0; jp < 2; jp++) {
                uint32_t off = SMEM_SWIZZLE_128B((wn * 32 + jp * 16 + bp_row) * 128 + kB + bp_cb);
                uint32_t r4[4];
                ldsm_x4(r4, sBh + off);
                bh[2 * jp][0] = r4[0]; bh[2 * jp][1] = r4[1];
                bh[2 * jp + 1][0] = r4[2]; bh[2 * jp + 1][1] = r4[3];
                ldsm_x4(r4, sBl + off);
                bl[2 * jp][0] = r4[0]; bl[2 * jp][1] = r4[1];
                bl[2 * jp + 1][0] = r4[2]; bl[2 * jp + 1][1] = r4[3];
            }
#pragma unroll
            for (int i = 0; i < 4; i++)
#pragma unroll
                for (int j = 0; j < 4; j++) mma_bf16(acc[i][j], ah[i], bh[j]);
#pragma unroll
            for (int i = 0; i < 4; i++)
#pragma unroll
                for (int j = 0; j < 4; j++) mma_bf16(acc[i][j], ah[i], bl[j]);
#pragma unroll
            for (int i = 0; i < 4; i++)
#pragma unroll
                for (int j = 0; j < 4; j++) mma_bf16(acc[i][j], al[i], bh[j]);
        }
        __syncthreads();
    }

    int r4i = lane >> 2;
    int cp2 = (lane & 3) * 2;

    if (mode == 1) {
#pragma unroll
        for (int i = 0; i < 4; i++)
#pragma unroll
            for (int j = 0; j < 4; j++) {
                int n = n0 + wn * 32 + j * 8 + cp2;
#pragma unroll
                for (int rr = 0; rr < 2; rr++) {
                    int m = m0 + wm * 64 + i * 16 + r4i + rr * 8;
                    *(float2*)(out + (size_t)m * C_ + n) =
                        make_float2(acc[i][j][rr * 2], acc[i][j][rr * 2 + 1]);
                }
            }
    } else {
        int which = n0 >> 10;
        __nv_bfloat16* dh = (which == 0) ? g_qh : (which == 1) ? g_kh : g_vh;
        __nv_bfloat16* dl = (which == 0) ? g_ql : (which == 1) ? g_kl : g_vl;
        float scale = (which == 0) ? 0.125f : 1.0f;
#pragma unroll
        for (int i = 0; i < 4; i++)
#pragma unroll
            for (int j = 0; j < 4; j++) {
                int n = n0 + wn * 32 + j * 8 + cp2;
                int h = (n & 1023) >> 6;
                int d = n & 63;
#pragma unroll
                for (int rr = 0; rr < 2; rr++) {
                    int m = m0 + wm * 64 + i * 16 + r4i + rr * 8;
                    int b = m >> 11;
                    int t = m & 2047;
                    size_t off = (size_t)(((b << 4) + h) * T_ + t) * DH_ + d;
                    float v0 = acc[i][j][rr * 2] * scale;
                    float v1 = acc[i][j][rr * 2 + 1] * scale;
                    __nv_bfloat16 h0 = __float2bfloat16(v0);
                    __nv_bfloat16 h1 = __float2bfloat16(v1);
                    float l0 = v0 - __bfloat162float(h0);
                    float l1 = v1 - __bfloat162float(h1);
                    uint16_t u0, u1;
                    memcpy(&u0, &h0, 2); memcpy(&u1, &h1, 2);
                    *(uint32_t*)(dh + off) = (uint32_t)u0 | ((uint32_t)u1 << 16);
                    *(uint32_t*)(dl + off) = cvt_bf16x2(l1, l0);
                }
            }
    }
}

// ---------------------------------------------------------------------------
// Tensor-core causal flash attention (round-4 structure).
// ---------------------------------------------------------------------------
#define AS_QH 0
#define AS_QL 16384
#define AS_KV 32768
#define AS_TOTAL (32768 + 2 * 32768)   // 98304

__global__ __launch_bounds__(256) void attn_mma_kernel()
{
    extern __shared__ char smem[];
    uint32_t sb = smem_to_u32(smem);
    int tid = threadIdx.x;
    int wid = tid >> 5;
    int lane = tid & 31;

    int qt = blockIdx.x;
    int bh = blockIdx.y;
    int q0 = qt * 128;
    size_t base = (size_t)bh * T_ * DH_;
    int nkt = 2 * qt + 2;

#pragma unroll
    for (int p = 0; p < 4; p++) {
        int idx = tid + p * 256;
        int row = idx >> 3;
        int ch  = idx & 7;
        uint32_t so = SMEM_SWIZZLE_128B(row * 128 + ch * 16);
        size_t g = base + (size_t)(q0 + row) * DH_ + ch * 8;
        cp16(sb + AS_QH + so, g_qh + g);
        cp16(sb + AS_QL + so, g_ql + g);
    }
    cp_commit();

    auto load_kv = [&](int j, int s) {
        uint32_t st = sb + AS_KV + s * 32768;
#pragma unroll
        for (int p = 0; p < 2; p++) {
            int idx = tid + p * 256;
            int row = idx >> 3;
            int ch  = idx & 7;
            uint32_t so = SMEM_SWIZZLE_128B(row * 128 + ch * 16);
            size_t g = base + (size_t)(j * 64 + row) * DH_ + ch * 8;
            cp16(st + so,         g_kh + g);
            cp16(st + 8192 + so,  g_kl + g);
            cp16(st + 16384 + so, g_vh + g);
            cp16(st + 24576 + so, g_vl + g);
        }
        cp_commit();
    };

    load_kv(0, 0);

    uint32_t qh[4][4], ql[4][4];
    float O[8][4];
#pragma unroll
    for (int dt = 0; dt < 8; dt++)
#pragma unroll
        for (int c = 0; c < 4; c++) O[dt][c] = 0.f;
    float m0r = -1e30f, m1r = -1e30f, l0r = 0.f, l1r = 0.f;

    int g4 = lane >> 2;
    int c2 = 2 * (lane & 3);
    int a_row = lane & 15;
    int a_cb  = (lane >> 4) << 4;
    int b_row = lane & 7;
    int b_cb  = ((lane >> 3) & 1) << 4;
    int v_row = (lane & 7) + ((lane >> 3) & 1) * 8;

    for (int j = 0; j < nkt; j++) {
        int s = j & 1;
        if (j + 1 < nkt) {
            load_kv(j + 1, (j + 1) & 1);
            asm volatile("cp.async.wait_group 1;" ::: "memory");
        } else {
            asm volatile("cp.async.wait_group 0;" ::: "memory");
        }
        __syncthreads();

        if (j == 0) {
#pragma unroll
            for (int ks = 0; ks < 4; ks++) {
                uint32_t off = SMEM_SWIZZLE_128B((wid * 16 + a_row) * 128 + ks * 32 + a_cb);
                ldsm_x4(qh[ks], sb + AS_QH + off);
                ldsm_x4(ql[ks], sb + AS_QL + off);
            }
        }

        uint32_t stK = sb + AS_KV + s * 32768;
        uint32_t stV = stK + 16384;

        float S[8][4];
#pragma unroll
        for (int jt = 0; jt < 8; jt++) {
#pragma unroll
            for (int c = 0; c < 4; c++) S[jt][c] = 0.f;
#pragma unroll
            for (int ks = 0; ks < 4; ks++) {
                uint32_t off = SMEM_SWIZZLE_128B((jt * 8 + b_row) * 128 + ks * 32 + b_cb);
                uint32_t kh[2], kl[2];
                ldsm_x2(kh, stK + off);
                ldsm_x2(kl, stK + 8192 + off);
                mma_bf16(S[jt], qh[ks], kh);
                mma_bf16(S[jt], qh[ks], kl);
                mma_bf16(S[jt], ql[ks], kh);
            }
        }

        if (j >= 2 * qt) {
            int r0 = q0 + wid * 16 + g4;
            int cb = j * 64 + c2;
#pragma unroll
            for (int jt = 0; jt < 8; jt++) {
                int c0 = cb + jt * 8;
                if (c0 > r0)     S[jt][0] = -1e30f;
                if (c0 + 1 > r0) S[jt][1] = -1e30f;
                if (c0 > r0 + 8)     S[jt][2] = -1e30f;
                if (c0 + 1 > r0 + 8) S[jt][3] = -1e30f;
            }
        }

        float mx0 = -1e30f, mx1 = -1e30f;
#pragma unroll
        for (int jt = 0; jt < 8; jt++) {
            mx0 = fmaxf(mx0, fmaxf(S[jt][0], S[jt][1]));
            mx1 = fmaxf(mx1, fmaxf(S[jt][2], S[jt][3]));
        }
        mx0 = fmaxf(mx0, __shfl_xor_sync(0xffffffffu, mx0, 1));
        mx0 = fmaxf(mx0, __shfl_xor_sync(0xffffffffu, mx0, 2));
        mx1 = fmaxf(mx1, __shfl_xor_sync(0xffffffffu, mx1, 1));
        mx1 = fmaxf(mx1, __shfl_xor_sync(0xffffffffu, mx1, 2));

        float mn0 = fmaxf(m0r, mx0), mn1 = fmaxf(m1r, mx1);
        float al0 = __expf(m0r - mn0), al1 = __expf(m1r - mn1);
        m0r = mn0; m1r = mn1;

        float s0 = 0.f, s1 = 0.f;
#pragma unroll
        for (int jt = 0; jt < 8; jt++) {
            S[jt][0] = __expf(S[jt][0] - mn0); s0 += S[jt][0];
            S[jt][1] = __expf(S[jt][1] - mn0); s0 += S[jt][1];
            S[jt][2] = __expf(S[jt][2] - mn1); s1 += S[jt][2];
            S[jt][3] = __expf(S[jt][3] - mn1); s1 += S[jt][3];
        }
        s0 += __shfl_xor_sync(0xffffffffu, s0, 1);
        s0 += __shfl_xor_sync(0xffffffffu, s0, 2);
        s1 += __shfl_xor_sync(0xffffffffu, s1, 1);
        s1 += __shfl_xor_sync(0xffffffffu, s1, 2);
        l0r = l0r * al0 + s0;
        l1r = l1r * al1 + s1;

#pragma unroll
        for (int dt = 0; dt < 8; dt++) {
            O[dt][0] *= al0; O[dt][1] *= al0;
            O[dt][2] *= al1; O[dt][3] *= al1;
        }

        uint32_t aPh[4][4], aPl[4][4];
#pragma unroll
        for (int ks2 = 0; ks2 < 4; ks2++) {
#pragma unroll
            for (int q = 0; q < 4; q++) {
                int tile = 2 * ks2 + (q >> 1);
                int cb = (q & 1) * 2;
                float p0 = S[tile][cb], p1 = S[tile][cb + 1];
                uint32_t t0 = __float_as_uint(p0) & 0xFFFF0000u;
                uint32_t t1 = __float_as_uint(p1) & 0xFFFF0000u;
                aPh[ks2][q] = (t0 >> 16) | t1;
                aPl[ks2][q] = cvt_bf16x2(p1 - __uint_as_float(t1),
                                         p0 - __uint_as_float(t0));
            }
        }

#pragma unroll
        for (int dt = 0; dt < 8; dt++) {
#pragma unroll
            for (int ks2 = 0; ks2 < 4; ks2++) {
                uint32_t off = SMEM_SWIZZLE_128B((ks2 * 16 + v_row) * 128 + dt * 16);
                uint32_t vh[2], vl[2];
                ldsm_x2_trans(vh, stV + off);
                ldsm_x2_trans(vl, stV + 8192 + off);
                mma_bf16(O[dt], aPh[ks2], vh);
                mma_bf16(O[dt], aPh[ks2], vl);
                mma_bf16(O[dt], aPl[ks2], vh);
            }
        }
        __syncthreads();
    }

    float li0 = 1.f / l0r, li1 = 1.f / l1r;
    int b = bh >> 4, h = bh & 15;
    int r0 = q0 + wid * 16 + g4;
#pragma unroll
    for (int dt = 0; dt < 8; dt++) {
        int d = dt * 8 + c2;
        {
            float v0 = O[dt][0] * li0, v1 = O[dt][1] * li0;
            size_t off = (size_t)(b * T_ + r0) * C_ + h * DH_ + d;
            __nv_bfloat16 h0 = __float2bfloat16(v0), h1 = __float2bfloat16(v1);
            float lo0 = v0 - __bfloat162float(h0), lo1 = v1 - __bfloat162float(h1);
            uint16_t u0, u1; memcpy(&u0, &h0, 2); memcpy(&u1, &h1, 2);
            *(uint32_t*)(g_yh + off) = (uint32_t)u0 | ((uint32_t)u1 << 16);
            *(uint32_t*)(g_yl + off) = cvt_bf16x2(lo1, lo0);
        }
        {
            float v0 = O[dt][2] * li1, v1 = O[dt][3] * li1;
            size_t off = (size_t)(b * T_ + r0 + 8) * C_ + h * DH_ + d;
            __nv_bfloat16 h0 = __float2bfloat16(v0), h1 = __float2bfloat16(v1);
            float lo0 = v0 - __bfloat162float(h0), lo1 = v1 - __bfloat162float(h1);
            uint16_t u0, u1; memcpy(&u0, &h0, 2); memcpy(&u1, &h1, 2);
            *(uint32_t*)(g_yh + off) = (uint32_t)u0 | ((uint32_t)u1 << 16);
            *(uint32_t*)(g_yl + off) = cvt_bf16x2(lo1, lo0);
        }
    }
}

// ---------------------------------------------------------------------------
extern "C" void kernel_launch(void* const* d_in, const int* in_sizes, int n_in,
                              void* d_out, int out_size)
{
    const float* x      = (const float*)d_in[0];
    const float* w_qkv  = (const float*)d_in[1];
    const float* w_proj = (const float*)d_in[2];
    float* out = (float*)d_out;
    (void)in_sizes; (void)n_in; (void)out_size;

    cudaFuncSetAttribute(mma_gemm_kernel,
                         cudaFuncAttributeMaxDynamicSharedMemorySize, SM_GEMM_TOTAL);
    cudaFuncSetAttribute(attn_mma_kernel,
                         cudaFuncAttributeMaxDynamicSharedMemorySize, AS_TOTAL);

    __nv_bfloat16 *xh, *xl, *yh, *yl, *wqh, *wql, *wph, *wpl;
    cudaGetSymbolAddress((void**)&xh,  g_xh);
    cudaGetSymbolAddress((void**)&xl,  g_xl);
    cudaGetSymbolAddress((void**)&yh,  g_yh);
    cudaGetSymbolAddress((void**)&yl,  g_yl);
    cudaGetSymbolAddress((void**)&wqh, g_wqkvTh);
    cudaGetSymbolAddress((void**)&wql, g_wqkvTl);
    cudaGetSymbolAddress((void**)&wph, g_wprojTh);
    cudaGetSymbolAddress((void**)&wpl, g_wprojTl);

    // prep
    convert_x_kernel<<<M_ * K_ / (256 * 4), 256>>>(x);
    transpose_w_kernel<<<dim3(N_QKV / 32, K_ / 32), dim3(32, 8)>>>(w_qkv, wqh, wql, N_QKV);
    transpose_w_kernel<<<dim3(C_ / 32, K_ / 32), dim3(32, 8)>>>(w_proj, wph, wpl, C_);

    // QKV GEMM with fused hi/lo split-scatter + q scale
    mma_gemm_kernel<<<dim3(N_QKV / 128, M_ / 128), 256, SM_GEMM_TOTAL>>>(
        xh, xl, wqh, wql, nullptr, 0);

    // tensor-core causal flash attention
    attn_mma_kernel<<<dim3(T_ / 128, B_ * H_), 256, AS_TOTAL>>>();

    // output projection GEMM
    mma_gemm_kernel<<<dim3(C_ / 128, M_ / 128), 256, SM_GEMM_TOTAL>>>(
        yh, yl, wph, wpl, out, 1);
}

// round 7
// speedup vs baseline: 1.1183x; 1.0924x over previous
#include <cuda_runtime.h>
#include <cuda_bf16.h>
#include <cstdint>

// Problem constants
#define B_   4
#define T_   2048
#define C_   1024
#define H_   16
#define DH_  64
#define M_   (B_ * T_)          // 8192
#define N_QKV (3 * C_)          // 3072
#define K_   1024

// ---------------------------------------------------------------------------
// Device-global scratch (allocation-free rule)
// ---------------------------------------------------------------------------
__device__ __nv_bfloat16 g_qh[B_ * H_ * T_ * DH_];
__device__ __nv_bfloat16 g_ql[B_ * H_ * T_ * DH_];
__device__ __nv_bfloat16 g_kh[B_ * H_ * T_ * DH_];
__device__ __nv_bfloat16 g_kl[B_ * H_ * T_ * DH_];
__device__ __nv_bfloat16 g_vh[B_ * H_ * T_ * DH_];
__device__ __nv_bfloat16 g_vl[B_ * H_ * T_ * DH_];
__device__ __nv_bfloat16 g_xh[M_ * K_];
__device__ __nv_bfloat16 g_xl[M_ * K_];
__device__ __nv_bfloat16 g_yh[M_ * C_];
__device__ __nv_bfloat16 g_yl[M_ * C_];
__device__ __nv_bfloat16 g_wqkvTh[N_QKV * K_];   // [N][K]
__device__ __nv_bfloat16 g_wqkvTl[N_QKV * K_];
__device__ __nv_bfloat16 g_wprojTh[C_ * K_];
__device__ __nv_bfloat16 g_wprojTl[C_ * K_];

#define SMEM_SWIZZLE_128B(o) ((o) ^ (((o) >> 3) & 0x70))

__device__ __forceinline__ uint32_t smem_to_u32(const void* p) {
    uint32_t a;
    asm("{ .reg .u64 t; cvta.to.shared.u64 t, %1; cvt.u32.u64 %0, t; }" : "=r"(a) : "l"(p));
    return a;
}
__device__ __forceinline__ void cp16(uint32_t saddr, const void* g) {
    asm volatile("cp.async.cg.shared.global [%0], [%1], 16;" :: "r"(saddr), "l"(g));
}
__device__ __forceinline__ void cp_commit() {
    asm volatile("cp.async.commit_group;" ::: "memory");
}
__device__ __forceinline__ void ldsm_x4(uint32_t* r, uint32_t addr) {
    asm volatile("ldmatrix.sync.aligned.m8n8.x4.shared.b16 {%0,%1,%2,%3}, [%4];"
        : "=r"(r[0]), "=r"(r[1]), "=r"(r[2]), "=r"(r[3]) : "r"(addr));
}
__device__ __forceinline__ void ldsm_x2(uint32_t* r, uint32_t addr) {
    asm volatile("ldmatrix.sync.aligned.m8n8.x2.shared.b16 {%0,%1}, [%2];"
        : "=r"(r[0]), "=r"(r[1]) : "r"(addr));
}
__device__ __forceinline__ void ldsm_x2_trans(uint32_t* r, uint32_t addr) {
    asm volatile("ldmatrix.sync.aligned.m8n8.x2.trans.shared.b16 {%0,%1}, [%2];"
        : "=r"(r[0]), "=r"(r[1]) : "r"(addr));
}
__device__ __forceinline__ void mma_bf16(float* c, const uint32_t* a, const uint32_t* b) {
    asm volatile("mma.sync.aligned.m16n8k16.row.col.f32.bf16.bf16.f32 "
        "{%0,%1,%2,%3}, {%4,%5,%6,%7}, {%8,%9}, {%0,%1,%2,%3};"
        : "+f"(c[0]), "+f"(c[1]), "+f"(c[2]), "+f"(c[3])
        : "r"(a[0]), "r"(a[1]), "r"(a[2]), "r"(a[3]), "r"(b[0]), "r"(b[1]));
}
__device__ __forceinline__ uint32_t cvt_bf16x2(float hi, float lo) {
    uint32_t d;
    asm("cvt.rn.bf16x2.f32 %0, %1, %2;" : "=r"(d) : "f"(hi), "f"(lo));
    return d;
}

// ---------------------------------------------------------------------------
// Prep: split x (fp32) into bf16 hi/lo
// ---------------------------------------------------------------------------
__global__ __launch_bounds__(256) void convert_x_kernel(const float* __restrict__ x)
{
    int idx = (blockIdx.x * 256 + threadIdx.x) * 4;
    float4 v = *(const float4*)(x + idx);
    __nv_bfloat16 h[4], l[4];
    float vv[4] = {v.x, v.y, v.z, v.w};
#pragma unroll
    for (int i = 0; i < 4; i++) {
        h[i] = __float2bfloat16(vv[i]);
        l[i] = __float2bfloat16(vv[i] - __bfloat162float(h[i]));
    }
    *(uint2*)(g_xh + idx) = *(uint2*)h;
    *(uint2*)(g_xl + idx) = *(uint2*)l;
}

// ---------------------------------------------------------------------------
// Prep: transpose W [K,N] -> WT hi/lo [N,K] bf16
// ---------------------------------------------------------------------------
__global__ __launch_bounds__(256) void transpose_w_kernel(
    const float* __restrict__ W, __nv_bfloat16* __restrict__ WTh,
    __nv_bfloat16* __restrict__ WTl, int N)
{
    __shared__ float t[32][33];
    int n0 = blockIdx.x * 32, k0 = blockIdx.y * 32;
    int tx = threadIdx.x, ty = threadIdx.y;
#pragma unroll
    for (int i = 0; i < 4; i++)
        t[ty + i * 8][tx] = W[(size_t)(k0 + ty + i * 8) * N + n0 + tx];
    __syncthreads();
#pragma unroll
    for (int i = 0; i < 4; i++) {
        int n = n0 + ty + i * 8;
        int k = k0 + tx;
        float v = t[tx][ty + i * 8];
        __nv_bfloat16 h = __float2bfloat16(v);
        __nv_bfloat16 l = __float2bfloat16(v - __bfloat162float(h));
        WTh[(size_t)n * K_ + k] = h;
        WTl[(size_t)n * K_ + k] = l;
    }
}

// ---------------------------------------------------------------------------
// Tensor-core GEMM (3-term hi/lo split). C[M,N] = A[M,K] @ B[N,K]^T.
// CTA tile 128(M)x64(N), BK=64, 256 threads / 8 warps (4m x 2n),
// warp tile 32x32. Double-buffered 48KB stages; 96KB/CTA -> 2 CTAs/SM.
// __launch_bounds__(256,2) caps regs at 128 to guarantee 2 CTAs.
// mode 0: split-scatter to q/k/v; mode 1: f32 store.
// ---------------------------------------------------------------------------
#define STAGE_BYTES 49152      // Ah(16K) Al(16K) Bh(8K) Bl(8K)
#define SM_GEMM_TOTAL (2 * STAGE_BYTES)   // 98304

__global__ __launch_bounds__(256, 2) void mma_gemm_kernel(
    const __nv_bfloat16* __restrict__ Ah, const __nv_bfloat16* __restrict__ Al,
    const __nv_bfloat16* __restrict__ Bh, const __nv_bfloat16* __restrict__ Bl,
    float* __restrict__ out, int mode)
{
    extern __shared__ char smem[];
    uint32_t sbase = smem_to_u32(smem);

    int tid = threadIdx.x;
    int wid = tid >> 5;
    int lane = tid & 31;
    int wm = wid >> 1;          // 0..3 (m, 32 rows each)
    int wn = wid & 1;           // 0..1 (n, 32 cols each)

    int m0 = blockIdx.y * 128;
    int n0 = blockIdx.x * 64;

    float acc[2][4][4];
#pragma unroll
    for (int i = 0; i < 2; i++)
#pragma unroll
        for (int j = 0; j < 4; j++)
#pragma unroll
            for (int c = 0; c < 4; c++) acc[i][j][c] = 0.f;

    auto load_chunk = [&](int kt, int s) {
        uint32_t st = sbase + s * STAGE_BYTES;
        // A: 128 rows x 64 cols bf16 (128B rows), hi+lo
#pragma unroll
        for (int p = 0; p < 4; p++) {
            int idx = tid + p * 256;       // 0..1023
            int row = idx >> 3;
            int ch  = idx & 7;
            uint32_t so = SMEM_SWIZZLE_128B(row * 128 + ch * 16);
            size_t ka = (size_t)(m0 + row) * K_ + kt * 64 + ch * 8;
            cp16(st + so,         Ah + ka);
            cp16(st + 16384 + so, Al + ka);
        }
        // B: 64 rows x 64 cols, hi+lo
#pragma unroll
        for (int p = 0; p < 2; p++) {
            int idx = tid + p * 256;       // 0..511
            int row = idx >> 3;
            int ch  = idx & 7;
            uint32_t so = SMEM_SWIZZLE_128B(row * 128 + ch * 16);
            size_t kb = (size_t)(n0 + row) * K_ + kt * 64 + ch * 8;
            cp16(st + 32768 + so, Bh + kb);
            cp16(st + 40960 + so, Bl + kb);
        }
        cp_commit();
    };

    load_chunk(0, 0);

    int a_row = lane & 15;
    int a_cb  = (lane >> 4) << 4;
    // paired-B ldsm_x4: lanes 0-7 (tile jt,16B lo), 8-15 (jt,hi),
    // 16-23 (jt+1,lo), 24-31 (jt+1,hi)
    int bg     = lane >> 3;
    int bp_row = (lane & 7) + ((bg >> 1) << 3);
    int bp_cb  = (bg & 1) << 4;

    for (int kt = 0; kt < 16; kt++) {
        int s = kt & 1;
        if (kt + 1 < 16) {
            load_chunk(kt + 1, (kt + 1) & 1);
            asm volatile("cp.async.wait_group 1;" ::: "memory");
        } else {
            asm volatile("cp.async.wait_group 0;" ::: "memory");
        }
        __syncthreads();

        uint32_t sAh = sbase + s * STAGE_BYTES;
        uint32_t sAl = sAh + 16384;
        uint32_t sBh = sAh + 32768;
        uint32_t sBl = sAh + 40960;

#pragma unroll
        for (int ks = 0; ks < 4; ks++) {
            int kB = ks * 32;
            uint32_t ah[2][4], al[2][4], bh[4][2], bl[4][2];
#pragma unroll
            for (int i = 0; i < 2; i++) {
                uint32_t off = SMEM_SWIZZLE_128B((wm * 32 + i * 16 + a_row) * 128 + kB + a_cb);
                ldsm_x4(ah[i], sAh + off);
                ldsm_x4(al[i], sAl + off);
            }
#pragma unroll
            for (int jp = 0; jp < 2; jp++) {
                uint32_t off = SMEM_SWIZZLE_128B((wn * 32 + jp * 16 + bp_row) * 128 + kB + bp_cb);
                uint32_t r4[4];
                ldsm_x4(r4, sBh + off);
                bh[2 * jp][0] = r4[0]; bh[2 * jp][1] = r4[1];
                bh[2 * jp + 1][0] = r4[2]; bh[2 * jp + 1][1] = r4[3];
                ldsm_x4(r4, sBl + off);
                bl[2 * jp][0] = r4[0]; bl[2 * jp][1] = r4[1];
                bl[2 * jp + 1][0] = r4[2]; bl[2 * jp + 1][1] = r4[3];
            }
#pragma unroll
            for (int i = 0; i < 2; i++)
#pragma unroll
                for (int j = 0; j < 4; j++) mma_bf16(acc[i][j], ah[i], bh[j]);
#pragma unroll
            for (int i = 0; i < 2; i++)
#pragma unroll
                for (int j = 0; j < 4; j++) mma_bf16(acc[i][j], ah[i], bl[j]);
#pragma unroll
            for (int i = 0; i < 2; i++)
#pragma unroll
                for (int j = 0; j < 4; j++) mma_bf16(acc[i][j], al[i], bh[j]);
        }
        __syncthreads();
    }

    int r4i = lane >> 2;
    int cp2 = (lane & 3) * 2;

    if (mode == 1) {
#pragma unroll
        for (int i = 0; i < 2; i++)
#pragma unroll
            for (int j = 0; j < 4; j++) {
                int n = n0 + wn * 32 + j * 8 + cp2;
#pragma unroll
                for (int rr = 0; rr < 2; rr++) {
                    int m = m0 + wm * 32 + i * 16 + r4i + rr * 8;
                    *(float2*)(out + (size_t)m * C_ + n) =
                        make_float2(acc[i][j][rr * 2], acc[i][j][rr * 2 + 1]);
                }
            }
    } else {
        int which = n0 >> 10;     // constant per CTA (64 | 1024)
        __nv_bfloat16* dh = (which == 0) ? g_qh : (which == 1) ? g_kh : g_vh;
        __nv_bfloat16* dl = (which == 0) ? g_ql : (which == 1) ? g_kl : g_vl;
        float scale = (which == 0) ? 0.125f : 1.0f;
#pragma unroll
        for (int i = 0; i < 2; i++)
#pragma unroll
            for (int j = 0; j < 4; j++) {
                int n = n0 + wn * 32 + j * 8 + cp2;
                int h = (n & 1023) >> 6;
                int d = n & 63;
#pragma unroll
                for (int rr = 0; rr < 2; rr++) {
                    int m = m0 + wm * 32 + i * 16 + r4i + rr * 8;
                    int b = m >> 11;
                    int t = m & 2047;
                    size_t off = (size_t)(((b << 4) + h) * T_ + t) * DH_ + d;
                    float v0 = acc[i][j][rr * 2] * scale;
                    float v1 = acc[i][j][rr * 2 + 1] * scale;
                    __nv_bfloat16 h0 = __float2bfloat16(v0);
                    __nv_bfloat16 h1 = __float2bfloat16(v1);
                    float l0 = v0 - __bfloat162float(h0);
                    float l1 = v1 - __bfloat162float(h1);
                    uint16_t u0, u1;
                    memcpy(&u0, &h0, 2); memcpy(&u1, &h1, 2);
                    *(uint32_t*)(dh + off) = (uint32_t)u0 | ((uint32_t)u1 << 16);
                    *(uint32_t*)(dl + off) = cvt_bf16x2(l1, l0);
                }
            }
    }
}

// ---------------------------------------------------------------------------
// Tensor-core causal flash attention (round-4 structure, unchanged).
// ---------------------------------------------------------------------------
#define AS_QH 0
#define AS_QL 16384
#define AS_KV 32768
#define AS_TOTAL (32768 + 2 * 32768)   // 98304

__global__ __launch_bounds__(256) void attn_mma_kernel()
{
    extern __shared__ char smem[];
    uint32_t sb = smem_to_u32(smem);
    int tid = threadIdx.x;
    int wid = tid >> 5;
    int lane = tid & 31;

    int qt = blockIdx.x;
    int bh = blockIdx.y;
    int q0 = qt * 128;
    size_t base = (size_t)bh * T_ * DH_;
    int nkt = 2 * qt + 2;

#pragma unroll
    for (int p = 0; p < 4; p++) {
        int idx = tid + p * 256;
        int row = idx >> 3;
        int ch  = idx & 7;
        uint32_t so = SMEM_SWIZZLE_128B(row * 128 + ch * 16);
        size_t g = base + (size_t)(q0 + row) * DH_ + ch * 8;
        cp16(sb + AS_QH + so, g_qh + g);
        cp16(sb + AS_QL + so, g_ql + g);
    }
    cp_commit();

    auto load_kv = [&](int j, int s) {
        uint32_t st = sb + AS_KV + s * 32768;
#pragma unroll
        for (int p = 0; p < 2; p++) {
            int idx = tid + p * 256;
            int row = idx >> 3;
            int ch  = idx & 7;
            uint32_t so = SMEM_SWIZZLE_128B(row * 128 + ch * 16);
            size_t g = base + (size_t)(j * 64 + row) * DH_ + ch * 8;
            cp16(st + so,         g_kh + g);
            cp16(st + 8192 + so,  g_kl + g);
            cp16(st + 16384 + so, g_vh + g);
            cp16(st + 24576 + so, g_vl + g);
        }
        cp_commit();
    };

    load_kv(0, 0);

    uint32_t qh[4][4], ql[4][4];
    float O[8][4];
#pragma unroll
    for (int dt = 0; dt < 8; dt++)
#pragma unroll
        for (int c = 0; c < 4; c++) O[dt][c] = 0.f;
    float m0r = -1e30f, m1r = -1e30f, l0r = 0.f, l1r = 0.f;

    int g4 = lane >> 2;
    int c2 = 2 * (lane & 3);
    int a_row = lane & 15;
    int a_cb  = (lane >> 4) << 4;
    int b_row = lane & 7;
    int b_cb  = ((lane >> 3) & 1) << 4;
    int v_row = (lane & 7) + ((lane >> 3) & 1) * 8;

    for (int j = 0; j < nkt; j++) {
        int s = j & 1;
        if (j + 1 < nkt) {
            load_kv(j + 1, (j + 1) & 1);
            asm volatile("cp.async.wait_group 1;" ::: "memory");
        } else {
            asm volatile("cp.async.wait_group 0;" ::: "memory");
        }
        __syncthreads();

        if (j == 0) {
#pragma unroll
            for (int ks = 0; ks < 4; ks++) {
                uint32_t off = SMEM_SWIZZLE_128B((wid * 16 + a_row) * 128 + ks * 32 + a_cb);
                ldsm_x4(qh[ks], sb + AS_QH + off);
                ldsm_x4(ql[ks], sb + AS_QL + off);
            }
        }

        uint32_t stK = sb + AS_KV + s * 32768;
        uint32_t stV = stK + 16384;

        float S[8][4];
#pragma unroll
        for (int jt = 0; jt < 8; jt++) {
#pragma unroll
            for (int c = 0; c < 4; c++) S[jt][c] = 0.f;
#pragma unroll
            for (int ks = 0; ks < 4; ks++) {
                uint32_t off = SMEM_SWIZZLE_128B((jt * 8 + b_row) * 128 + ks * 32 + b_cb);
                uint32_t kh[2], kl[2];
                ldsm_x2(kh, stK + off);
                ldsm_x2(kl, stK + 8192 + off);
                mma_bf16(S[jt], qh[ks], kh);
                mma_bf16(S[jt], qh[ks], kl);
                mma_bf16(S[jt], ql[ks], kh);
            }
        }

        if (j >= 2 * qt) {
            int r0 = q0 + wid * 16 + g4;
            int cb = j * 64 + c2;
#pragma unroll
            for (int jt = 0; jt < 8; jt++) {
                int c0 = cb + jt * 8;
                if (c0 > r0)     S[jt][0] = -1e30f;
                if (c0 + 1 > r0) S[jt][1] = -1e30f;
                if (c0 > r0 + 8)     S[jt][2] = -1e30f;
                if (c0 + 1 > r0 + 8) S[jt][3] = -1e30f;
            }
        }

        float mx0 = -1e30f, mx1 = -1e30f;
#pragma unroll
        for (int jt = 0; jt < 8; jt++) {
            mx0 = fmaxf(mx0, fmaxf(S[jt][0], S[jt][1]));
            mx1 = fmaxf(mx1, fmaxf(S[jt][2], S[jt][3]));
        }
        mx0 = fmaxf(mx0, __shfl_xor_sync(0xffffffffu, mx0, 1));
        mx0 = fmaxf(mx0, __shfl_xor_sync(0xffffffffu, mx0, 2));
        mx1 = fmaxf(mx1, __shfl_xor_sync(0xffffffffu, mx1, 1));
        mx1 = fmaxf(mx1, __shfl_xor_sync(0xffffffffu, mx1, 2));

        float mn0 = fmaxf(m0r, mx0), mn1 = fmaxf(m1r, mx1);
        float al0 = __expf(m0r - mn0), al1 = __expf(m1r - mn1);
        m0r = mn0; m1r = mn1;

        float s0 = 0.f, s1 = 0.f;
#pragma unroll
        for (int jt = 0; jt < 8; jt++) {
            S[jt][0] = __expf(S[jt][0] - mn0); s0 += S[jt][0];
            S[jt][1] = __expf(S[jt][1] - mn0); s0 += S[jt][1];
            S[jt][2] = __expf(S[jt][2] - mn1); s1 += S[jt][2];
            S[jt][3] = __expf(S[jt][3] - mn1); s1 += S[jt][3];
        }
        s0 += __shfl_xor_sync(0xffffffffu, s0, 1);
        s0 += __shfl_xor_sync(0xffffffffu, s0, 2);
        s1 += __shfl_xor_sync(0xffffffffu, s1, 1);
        s1 += __shfl_xor_sync(0xffffffffu, s1, 2);
        l0r = l0r * al0 + s0;
        l1r = l1r * al1 + s1;

#pragma unroll
        for (int dt = 0; dt < 8; dt++) {
            O[dt][0] *= al0; O[dt][1] *= al0;
            O[dt][2] *= al1; O[dt][3] *= al1;
        }

        uint32_t aPh[4][4], aPl[4][4];
#pragma unroll
        for (int ks2 = 0; ks2 < 4; ks2++) {
#pragma unroll
            for (int q = 0; q < 4; q++) {
                int tile = 2 * ks2 + (q >> 1);
                int cb = (q & 1) * 2;
                float p0 = S[tile][cb], p1 = S[tile][cb + 1];
                uint32_t t0 = __float_as_uint(p0) & 0xFFFF0000u;
                uint32_t t1 = __float_as_uint(p1) & 0xFFFF0000u;
                aPh[ks2][q] = (t0 >> 16) | t1;
                aPl[ks2][q] = cvt_bf16x2(p1 - __uint_as_float(t1),
                                         p0 - __uint_as_float(t0));
            }
        }

#pragma unroll
        for (int dt = 0; dt < 8; dt++) {
#pragma unroll
            for (int ks2 = 0; ks2 < 4; ks2++) {
                uint32_t off = SMEM_SWIZZLE_128B((ks2 * 16 + v_row) * 128 + dt * 16);
                uint32_t vh[2], vl[2];
                ldsm_x2_trans(vh, stV + off);
                ldsm_x2_trans(vl, stV + 8192 + off);
                mma_bf16(O[dt], aPh[ks2], vh);
                mma_bf16(O[dt], aPh[ks2], vl);
                mma_bf16(O[dt], aPl[ks2], vh);
            }
        }
        __syncthreads();
    }

    float li0 = 1.f / l0r, li1 = 1.f / l1r;
    int b = bh >> 4, h = bh & 15;
    int r0 = q0 + wid * 16 + g4;
#pragma unroll
    for (int dt = 0; dt < 8; dt++) {
        int d = dt * 8 + c2;
        {
            float v0 = O[dt][0] * li0, v1 = O[dt][1] * li0;
            size_t off = (size_t)(b * T_ + r0) * C_ + h * DH_ + d;
            __nv_bfloat16 h0 = __float2bfloat16(v0), h1 = __float2bfloat16(v1);
            float lo0 = v0 - __bfloat162float(h0), lo1 = v1 - __bfloat162float(h1);
            uint16_t u0, u1; memcpy(&u0, &h0, 2); memcpy(&u1, &h1, 2);
            *(uint32_t*)(g_yh + off) = (uint32_t)u0 | ((uint32_t)u1 << 16);
            *(uint32_t*)(g_yl + off) = cvt_bf16x2(lo1, lo0);
        }
        {
            float v0 = O[dt][2] * li1, v1 = O[dt][3] * li1;
            size_t off = (size_t)(b * T_ + r0 + 8) * C_ + h * DH_ + d;
            __nv_bfloat16 h0 = __float2bfloat16(v0), h1 = __float2bfloat16(v1);
            float lo0 = v0 - __bfloat162float(h0), lo1 = v1 - __bfloat162float(h1);
            uint16_t u0, u1; memcpy(&u0, &h0, 2); memcpy(&u1, &h1, 2);
            *(uint32_t*)(g_yh + off) = (uint32_t)u0 | ((uint32_t)u1 << 16);
            *(uint32_t*)(g_yl + off) = cvt_bf16x2(lo1, lo0);
        }
    }
}

// ---------------------------------------------------------------------------
extern "C" void kernel_launch(void* const* d_in, const int* in_sizes, int n_in,
                              void* d_out, int out_size)
{
    const float* x      = (const float*)d_in[0];
    const float* w_qkv  = (const float*)d_in[1];
    const float* w_proj = (const float*)d_in[2];
    float* out = (float*)d_out;
    (void)in_sizes; (void)n_in; (void)out_size;

    cudaFuncSetAttribute(mma_gemm_kernel,
                         cudaFuncAttributeMaxDynamicSharedMemorySize, SM_GEMM_TOTAL);
    cudaFuncSetAttribute(attn_mma_kernel,
                         cudaFuncAttributeMaxDynamicSharedMemorySize, AS_TOTAL);

    __nv_bfloat16 *xh, *xl, *yh, *yl, *wqh, *wql, *wph, *wpl;
    cudaGetSymbolAddress((void**)&xh,  g_xh);
    cudaGetSymbolAddress((void**)&xl,  g_xl);
    cudaGetSymbolAddress((void**)&yh,  g_yh);
    cudaGetSymbolAddress((void**)&yl,  g_yl);
    cudaGetSymbolAddress((void**)&wqh, g_wqkvTh);
    cudaGetSymbolAddress((void**)&wql, g_wqkvTl);
    cudaGetSymbolAddress((void**)&wph, g_wprojTh);
    cudaGetSymbolAddress((void**)&wpl, g_wprojTl);

    // prep
    convert_x_kernel<<<M_ * K_ / (256 * 4), 256>>>(x);
    transpose_w_kernel<<<dim3(N_QKV / 32, K_ / 32), dim3(32, 8)>>>(w_qkv, wqh, wql, N_QKV);
    transpose_w_kernel<<<dim3(C_ / 32, K_ / 32), dim3(32, 8)>>>(w_proj, wph, wpl, C_);

    // QKV GEMM with fused hi/lo split-scatter + q scale
    mma_gemm_kernel<<<dim3(N_QKV / 64, M_ / 128), 256, SM_GEMM_TOTAL>>>(
        xh, xl, wqh, wql, nullptr, 0);

    // tensor-core causal flash attention
    attn_mma_kernel<<<dim3(T_ / 128, B_ * H_), 256, AS_TOTAL>>>();

    // output projection GEMM
    mma_gemm_kernel<<<dim3(C_ / 64, M_ / 128), 256, SM_GEMM_TOTAL>>>(
        yh, yl, wph, wpl, out, 1);
}

// round 8
// speedup vs baseline: 1.2069x; 1.0792x over previous
#include <cuda_runtime.h>
#include <cuda_bf16.h>
#include <cstdint>

// Problem constants
#define B_   4
#define T_   2048
#define C_   1024
#define H_   16
#define DH_  64
#define M_   (B_ * T_)          // 8192
#define N_QKV (3 * C_)          // 3072
#define K_   1024

// ---------------------------------------------------------------------------
// Device-global scratch (allocation-free rule)
// ---------------------------------------------------------------------------
__device__ __nv_bfloat16 g_qh[B_ * H_ * T_ * DH_];
__device__ __nv_bfloat16 g_ql[B_ * H_ * T_ * DH_];
__device__ __nv_bfloat16 g_kh[B_ * H_ * T_ * DH_];
__device__ __nv_bfloat16 g_kl[B_ * H_ * T_ * DH_];
__device__ __nv_bfloat16 g_vh[B_ * H_ * T_ * DH_];
__device__ __nv_bfloat16 g_vl[B_ * H_ * T_ * DH_];
__device__ __nv_bfloat16 g_xh[M_ * K_];
__device__ __nv_bfloat16 g_xl[M_ * K_];
__device__ __nv_bfloat16 g_yh[M_ * C_];
__device__ __nv_bfloat16 g_yl[M_ * C_];
__device__ __nv_bfloat16 g_wqkvTh[N_QKV * K_];   // [N][K]
__device__ __nv_bfloat16 g_wqkvTl[N_QKV * K_];
__device__ __nv_bfloat16 g_wprojTh[C_ * K_];
__device__ __nv_bfloat16 g_wprojTl[C_ * K_];

#define SMEM_SWIZZLE_128B(o) ((o) ^ (((o) >> 3) & 0x70))

__device__ __forceinline__ uint32_t smem_to_u32(const void* p) {
    uint32_t a;
    asm("{ .reg .u64 t; cvta.to.shared.u64 t, %1; cvt.u32.u64 %0, t; }" : "=r"(a) : "l"(p));
    return a;
}
__device__ __forceinline__ void cp16(uint32_t saddr, const void* g) {
    asm volatile("cp.async.cg.shared.global [%0], [%1], 16;" :: "r"(saddr), "l"(g));
}
__device__ __forceinline__ void cp_commit() {
    asm volatile("cp.async.commit_group;" ::: "memory");
}
__device__ __forceinline__ void ldsm_x4(uint32_t* r, uint32_t addr) {
    asm volatile("ldmatrix.sync.aligned.m8n8.x4.shared.b16 {%0,%1,%2,%3}, [%4];"
        : "=r"(r[0]), "=r"(r[1]), "=r"(r[2]), "=r"(r[3]) : "r"(addr));
}
__device__ __forceinline__ void ldsm_x2(uint32_t* r, uint32_t addr) {
    asm volatile("ldmatrix.sync.aligned.m8n8.x2.shared.b16 {%0,%1}, [%2];"
        : "=r"(r[0]), "=r"(r[1]) : "r"(addr));
}
__device__ __forceinline__ void ldsm_x2_trans(uint32_t* r, uint32_t addr) {
    asm volatile("ldmatrix.sync.aligned.m8n8.x2.trans.shared.b16 {%0,%1}, [%2];"
        : "=r"(r[0]), "=r"(r[1]) : "r"(addr));
}
__device__ __forceinline__ void mma_bf16(float* c, const uint32_t* a, const uint32_t* b) {
    asm volatile("mma.sync.aligned.m16n8k16.row.col.f32.bf16.bf16.f32 "
        "{%0,%1,%2,%3}, {%4,%5,%6,%7}, {%8,%9}, {%0,%1,%2,%3};"
        : "+f"(c[0]), "+f"(c[1]), "+f"(c[2]), "+f"(c[3])
        : "r"(a[0]), "r"(a[1]), "r"(a[2]), "r"(a[3]), "r"(b[0]), "r"(b[1]));
}
__device__ __forceinline__ uint32_t cvt_bf16x2(float hi, float lo) {
    uint32_t d;
    asm("cvt.rn.bf16x2.f32 %0, %1, %2;" : "=r"(d) : "f"(hi), "f"(lo));
    return d;
}

// ---------------------------------------------------------------------------
// Prep: split x (fp32) into bf16 hi/lo
// ---------------------------------------------------------------------------
__global__ __launch_bounds__(256) void convert_x_kernel(const float* __restrict__ x)
{
    int idx = (blockIdx.x * 256 + threadIdx.x) * 4;
    float4 v = *(const float4*)(x + idx);
    __nv_bfloat16 h[4], l[4];
    float vv[4] = {v.x, v.y, v.z, v.w};
#pragma unroll
    for (int i = 0; i < 4; i++) {
        h[i] = __float2bfloat16(vv[i]);
        l[i] = __float2bfloat16(vv[i] - __bfloat162float(h[i]));
    }
    *(uint2*)(g_xh + idx) = *(uint2*)h;
    *(uint2*)(g_xl + idx) = *(uint2*)l;
}

// ---------------------------------------------------------------------------
// Prep: transpose W [K,N] -> WT hi/lo [N,K] bf16
// ---------------------------------------------------------------------------
__global__ __launch_bounds__(256) void transpose_w_kernel(
    const float* __restrict__ W, __nv_bfloat16* __restrict__ WTh,
    __nv_bfloat16* __restrict__ WTl, int N)
{
    __shared__ float t[32][33];
    int n0 = blockIdx.x * 32, k0 = blockIdx.y * 32;
    int tx = threadIdx.x, ty = threadIdx.y;
#pragma unroll
    for (int i = 0; i < 4; i++)
        t[ty + i * 8][tx] = W[(size_t)(k0 + ty + i * 8) * N + n0 + tx];
    __syncthreads();
#pragma unroll
    for (int i = 0; i < 4; i++) {
        int n = n0 + ty + i * 8;
        int k = k0 + tx;
        float v = t[tx][ty + i * 8];
        __nv_bfloat16 h = __float2bfloat16(v);
        __nv_bfloat16 l = __float2bfloat16(v - __bfloat162float(h));
        WTh[(size_t)n * K_ + k] = h;
        WTl[(size_t)n * K_ + k] = l;
    }
}

// ---------------------------------------------------------------------------
// Tensor-core GEMM (3-term hi/lo split). C[M,N] = A[M,K] @ B[N,K]^T.
// CTA tile 128(M)x64(N), BK=64, 256 threads / 8 warps (4m x 2n),
// warp tile 32x32. Double-buffered 48KB stages; 96KB/CTA -> 2 CTAs/SM.
// ---------------------------------------------------------------------------
#define STAGE_BYTES 49152      // Ah(16K) Al(16K) Bh(8K) Bl(8K)
#define SM_GEMM_TOTAL (2 * STAGE_BYTES)   // 98304

__global__ __launch_bounds__(256, 2) void mma_gemm_kernel(
    const __nv_bfloat16* __restrict__ Ah, const __nv_bfloat16* __restrict__ Al,
    const __nv_bfloat16* __restrict__ Bh, const __nv_bfloat16* __restrict__ Bl,
    float* __restrict__ out, int mode)
{
    extern __shared__ char smem[];
    uint32_t sbase = smem_to_u32(smem);

    int tid = threadIdx.x;
    int wid = tid >> 5;
    int lane = tid & 31;
    int wm = wid >> 1;          // 0..3
    int wn = wid & 1;           // 0..1

    int m0 = blockIdx.y * 128;
    int n0 = blockIdx.x * 64;

    float acc[2][4][4];
#pragma unroll
    for (int i = 0; i < 2; i++)
#pragma unroll
        for (int j = 0; j < 4; j++)
#pragma unroll
            for (int c = 0; c < 4; c++) acc[i][j][c] = 0.f;

    auto load_chunk = [&](int kt, int s) {
        uint32_t st = sbase + s * STAGE_BYTES;
#pragma unroll
        for (int p = 0; p < 4; p++) {
            int idx = tid + p * 256;
            int row = idx >> 3;
            int ch  = idx & 7;
            uint32_t so = SMEM_SWIZZLE_128B(row * 128 + ch * 16);
            size_t ka = (size_t)(m0 + row) * K_ + kt * 64 + ch * 8;
            cp16(st + so,         Ah + ka);
            cp16(st + 16384 + so, Al + ka);
        }
#pragma unroll
        for (int p = 0; p < 2; p++) {
            int idx = tid + p * 256;
            int row = idx >> 3;
            int ch  = idx & 7;
            uint32_t so = SMEM_SWIZZLE_128B(row * 128 + ch * 16);
            size_t kb = (size_t)(n0 + row) * K_ + kt * 64 + ch * 8;
            cp16(st + 32768 + so, Bh + kb);
            cp16(st + 40960 + so, Bl + kb);
        }
        cp_commit();
    };

    load_chunk(0, 0);

    int a_row = lane & 15;
    int a_cb  = (lane >> 4) << 4;
    int bg     = lane >> 3;
    int bp_row = (lane & 7) + ((bg >> 1) << 3);
    int bp_cb  = (bg & 1) << 4;

    for (int kt = 0; kt < 16; kt++) {
        int s = kt & 1;
        if (kt + 1 < 16) {
            load_chunk(kt + 1, (kt + 1) & 1);
            asm volatile("cp.async.wait_group 1;" ::: "memory");
        } else {
            asm volatile("cp.async.wait_group 0;" ::: "memory");
        }
        __syncthreads();

        uint32_t sAh = sbase + s * STAGE_BYTES;
        uint32_t sAl = sAh + 16384;
        uint32_t sBh = sAh + 32768;
        uint32_t sBl = sAh + 40960;

#pragma unroll
        for (int ks = 0; ks < 4; ks++) {
            int kB = ks * 32;
            uint32_t ah[2][4], al[2][4], bh[4][2], bl[4][2];
#pragma unroll
            for (int i = 0; i < 2; i++) {
                uint32_t off = SMEM_SWIZZLE_128B((wm * 32 + i * 16 + a_row) * 128 + kB + a_cb);
                ldsm_x4(ah[i], sAh + off);
                ldsm_x4(al[i], sAl + off);
            }
#pragma unroll
            for (int jp = 0; jp < 2; jp++) {
                uint32_t off = SMEM_SWIZZLE_128B((wn * 32 + jp * 16 + bp_row) * 128 + kB + bp_cb);
                uint32_t r4[4];
                ldsm_x4(r4, sBh + off);
                bh[2 * jp][0] = r4[0]; bh[2 * jp][1] = r4[1];
                bh[2 * jp + 1][0] = r4[2]; bh[2 * jp + 1][1] = r4[3];
                ldsm_x4(r4, sBl + off);
                bl[2 * jp][0] = r4[0]; bl[2 * jp][1] = r4[1];
                bl[2 * jp + 1][0] = r4[2]; bl[2 * jp + 1][1] = r4[3];
            }
#pragma unroll
            for (int i = 0; i < 2; i++)
#pragma unroll
                for (int j = 0; j < 4; j++) mma_bf16(acc[i][j], ah[i], bh[j]);
#pragma unroll
            for (int i = 0; i < 2; i++)
#pragma unroll
                for (int j = 0; j < 4; j++) mma_bf16(acc[i][j], ah[i], bl[j]);
#pragma unroll
            for (int i = 0; i < 2; i++)
#pragma unroll
                for (int j = 0; j < 4; j++) mma_bf16(acc[i][j], al[i], bh[j]);
        }
        __syncthreads();
    }

    int r4i = lane >> 2;
    int cp2 = (lane & 3) * 2;

    if (mode == 1) {
#pragma unroll
        for (int i = 0; i < 2; i++)
#pragma unroll
            for (int j = 0; j < 4; j++) {
                int n = n0 + wn * 32 + j * 8 + cp2;
#pragma unroll
                for (int rr = 0; rr < 2; rr++) {
                    int m = m0 + wm * 32 + i * 16 + r4i + rr * 8;
                    *(float2*)(out + (size_t)m * C_ + n) =
                        make_float2(acc[i][j][rr * 2], acc[i][j][rr * 2 + 1]);
                }
            }
    } else {
        int which = n0 >> 10;
        __nv_bfloat16* dh = (which == 0) ? g_qh : (which == 1) ? g_kh : g_vh;
        __nv_bfloat16* dl = (which == 0) ? g_ql : (which == 1) ? g_kl : g_vl;
        float scale = (which == 0) ? 0.125f : 1.0f;
#pragma unroll
        for (int i = 0; i < 2; i++)
#pragma unroll
            for (int j = 0; j < 4; j++) {
                int n = n0 + wn * 32 + j * 8 + cp2;
                int h = (n & 1023) >> 6;
                int d = n & 63;
#pragma unroll
                for (int rr = 0; rr < 2; rr++) {
                    int m = m0 + wm * 32 + i * 16 + r4i + rr * 8;
                    int b = m >> 11;
                    int t = m & 2047;
                    size_t off = (size_t)(((b << 4) + h) * T_ + t) * DH_ + d;
                    float v0 = acc[i][j][rr * 2] * scale;
                    float v1 = acc[i][j][rr * 2 + 1] * scale;
                    __nv_bfloat16 h0 = __float2bfloat16(v0);
                    __nv_bfloat16 h1 = __float2bfloat16(v1);
                    float l0 = v0 - __bfloat162float(h0);
                    float l1 = v1 - __bfloat162float(h1);
                    uint16_t u0, u1;
                    memcpy(&u0, &h0, 2); memcpy(&u1, &h1, 2);
                    *(uint32_t*)(dh + off) = (uint32_t)u0 | ((uint32_t)u1 << 16);
                    *(uint32_t*)(dl + off) = cvt_bf16x2(l1, l0);
                }
            }
    }
}

// ---------------------------------------------------------------------------
// Tensor-core causal flash attention.
// 2 CTAs/SM (forced): P-fragments packed in-place into S to cut registers.
// Grid: (bh, qt-descending) so the longest CTAs launch first (LPT packing).
// ---------------------------------------------------------------------------
#define AS_QH 0
#define AS_QL 16384
#define AS_KV 32768
#define AS_TOTAL (32768 + 2 * 32768)   // 98304

__global__ __launch_bounds__(256, 2) void attn_mma_kernel()
{
    extern __shared__ char smem[];
    uint32_t sb = smem_to_u32(smem);
    int tid = threadIdx.x;
    int wid = tid >> 5;
    int lane = tid & 31;

    int qt = 15 - blockIdx.y;     // descending: longest first
    int bh = blockIdx.x;
    int q0 = qt * 128;
    size_t base = (size_t)bh * T_ * DH_;
    int nkt = 2 * qt + 2;

#pragma unroll
    for (int p = 0; p < 4; p++) {
        int idx = tid + p * 256;
        int row = idx >> 3;
        int ch  = idx & 7;
        uint32_t so = SMEM_SWIZZLE_128B(row * 128 + ch * 16);
        size_t g = base + (size_t)(q0 + row) * DH_ + ch * 8;
        cp16(sb + AS_QH + so, g_qh + g);
        cp16(sb + AS_QL + so, g_ql + g);
    }
    cp_commit();

    auto load_kv = [&](int j, int s) {
        uint32_t st = sb + AS_KV + s * 32768;
#pragma unroll
        for (int p = 0; p < 2; p++) {
            int idx = tid + p * 256;
            int row = idx >> 3;
            int ch  = idx & 7;
            uint32_t so = SMEM_SWIZZLE_128B(row * 128 + ch * 16);
            size_t g = base + (size_t)(j * 64 + row) * DH_ + ch * 8;
            cp16(st + so,         g_kh + g);
            cp16(st + 8192 + so,  g_kl + g);
            cp16(st + 16384 + so, g_vh + g);
            cp16(st + 24576 + so, g_vl + g);
        }
        cp_commit();
    };

    load_kv(0, 0);

    uint32_t qh[4][4], ql[4][4];
    float O[8][4];
#pragma unroll
    for (int dt = 0; dt < 8; dt++)
#pragma unroll
        for (int c = 0; c < 4; c++) O[dt][c] = 0.f;
    float m0r = -1e30f, m1r = -1e30f, l0r = 0.f, l1r = 0.f;

    int g4 = lane >> 2;
    int c2 = 2 * (lane & 3);
    int a_row = lane & 15;
    int a_cb  = (lane >> 4) << 4;
    int b_row = lane & 7;
    int b_cb  = ((lane >> 3) & 1) << 4;
    int v_row = (lane & 7) + ((lane >> 3) & 1) * 8;

    for (int j = 0; j < nkt; j++) {
        int s = j & 1;
        if (j + 1 < nkt) {
            load_kv(j + 1, (j + 1) & 1);
            asm volatile("cp.async.wait_group 1;" ::: "memory");
        } else {
            asm volatile("cp.async.wait_group 0;" ::: "memory");
        }
        __syncthreads();

        if (j == 0) {
#pragma unroll
            for (int ks = 0; ks < 4; ks++) {
                uint32_t off = SMEM_SWIZZLE_128B((wid * 16 + a_row) * 128 + ks * 32 + a_cb);
                ldsm_x4(qh[ks], sb + AS_QH + off);
                ldsm_x4(ql[ks], sb + AS_QL + off);
            }
        }

        uint32_t stK = sb + AS_KV + s * 32768;
        uint32_t stV = stK + 16384;

        float S[8][4];
#pragma unroll
        for (int jt = 0; jt < 8; jt++) {
#pragma unroll
            for (int c = 0; c < 4; c++) S[jt][c] = 0.f;
#pragma unroll
            for (int ks = 0; ks < 4; ks++) {
                uint32_t off = SMEM_SWIZZLE_128B((jt * 8 + b_row) * 128 + ks * 32 + b_cb);
                uint32_t kh[2], kl[2];
                ldsm_x2(kh, stK + off);
                ldsm_x2(kl, stK + 8192 + off);
                mma_bf16(S[jt], qh[ks], kh);
                mma_bf16(S[jt], qh[ks], kl);
                mma_bf16(S[jt], ql[ks], kh);
            }
        }

        if (j >= 2 * qt) {
            int r0 = q0 + wid * 16 + g4;
            int cb = j * 64 + c2;
#pragma unroll
            for (int jt = 0; jt < 8; jt++) {
                int c0 = cb + jt * 8;
                if (c0 > r0)     S[jt][0] = -1e30f;
                if (c0 + 1 > r0) S[jt][1] = -1e30f;
                if (c0 > r0 + 8)     S[jt][2] = -1e30f;
                if (c0 + 1 > r0 + 8) S[jt][3] = -1e30f;
            }
        }

        float mx0 = -1e30f, mx1 = -1e30f;
#pragma unroll
        for (int jt = 0; jt < 8; jt++) {
            mx0 = fmaxf(mx0, fmaxf(S[jt][0], S[jt][1]));
            mx1 = fmaxf(mx1, fmaxf(S[jt][2], S[jt][3]));
        }
        mx0 = fmaxf(mx0, __shfl_xor_sync(0xffffffffu, mx0, 1));
        mx0 = fmaxf(mx0, __shfl_xor_sync(0xffffffffu, mx0, 2));
        mx1 = fmaxf(mx1, __shfl_xor_sync(0xffffffffu, mx1, 1));
        mx1 = fmaxf(mx1, __shfl_xor_sync(0xffffffffu, mx1, 2));

        float mn0 = fmaxf(m0r, mx0), mn1 = fmaxf(m1r, mx1);
        float al0 = __expf(m0r - mn0), al1 = __expf(m1r - mn1);
        m0r = mn0; m1r = mn1;

        float s0 = 0.f, s1 = 0.f;
#pragma unroll
        for (int jt = 0; jt < 8; jt++) {
            S[jt][0] = __expf(S[jt][0] - mn0); s0 += S[jt][0];
            S[jt][1] = __expf(S[jt][1] - mn0); s0 += S[jt][1];
            S[jt][2] = __expf(S[jt][2] - mn1); s1 += S[jt][2];
            S[jt][3] = __expf(S[jt][3] - mn1); s1 += S[jt][3];
        }
        s0 += __shfl_xor_sync(0xffffffffu, s0, 1);
        s0 += __shfl_xor_sync(0xffffffffu, s0, 2);
        s1 += __shfl_xor_sync(0xffffffffu, s1, 1);
        s1 += __shfl_xor_sync(0xffffffffu, s1, 2);
        l0r = l0r * al0 + s0;
        l1r = l1r * al1 + s1;

#pragma unroll
        for (int dt = 0; dt < 8; dt++) {
            O[dt][0] *= al0; O[dt][1] *= al0;
            O[dt][2] *= al1; O[dt][3] *= al1;
        }

        // ---- pack P hi/lo IN PLACE into S (S[tile][cb]=hi bits, [cb+1]=lo bits)
#pragma unroll
        for (int ks2 = 0; ks2 < 4; ks2++) {
#pragma unroll
            for (int q = 0; q < 4; q++) {
                int tile = 2 * ks2 + (q >> 1);
                int cb = (q & 1) * 2;
                float p0 = S[tile][cb], p1 = S[tile][cb + 1];
                uint32_t t0 = __float_as_uint(p0) & 0xFFFF0000u;
                uint32_t t1 = __float_as_uint(p1) & 0xFFFF0000u;
                S[tile][cb]     = __uint_as_float((t0 >> 16) | t1);
                S[tile][cb + 1] = __uint_as_float(cvt_bf16x2(p1 - __uint_as_float(t1),
                                                             p0 - __uint_as_float(t0)));
            }
        }

        // ---- O += P @ V (3-term), P frags re-read from packed S ----
#pragma unroll
        for (int dt = 0; dt < 8; dt++) {
#pragma unroll
            for (int ks2 = 0; ks2 < 4; ks2++) {
                uint32_t ph[4] = {
                    __float_as_uint(S[2 * ks2][0]),     __float_as_uint(S[2 * ks2][2]),
                    __float_as_uint(S[2 * ks2 + 1][0]), __float_as_uint(S[2 * ks2 + 1][2])};
                uint32_t pl[4] = {
                    __float_as_uint(S[2 * ks2][1]),     __float_as_uint(S[2 * ks2][3]),
                    __float_as_uint(S[2 * ks2 + 1][1]), __float_as_uint(S[2 * ks2 + 1][3])};
                uint32_t off = SMEM_SWIZZLE_128B((ks2 * 16 + v_row) * 128 + dt * 16);
                uint32_t vh[2], vl[2];
                ldsm_x2_trans(vh, stV + off);
                ldsm_x2_trans(vl, stV + 8192 + off);
                mma_bf16(O[dt], ph, vh);
                mma_bf16(O[dt], ph, vl);
                mma_bf16(O[dt], pl, vh);
            }
        }
        __syncthreads();
    }

    float li0 = 1.f / l0r, li1 = 1.f / l1r;
    int b = bh >> 4, h = bh & 15;
    int r0 = q0 + wid * 16 + g4;
#pragma unroll
    for (int dt = 0; dt < 8; dt++) {
        int d = dt * 8 + c2;
        {
            float v0 = O[dt][0] * li0, v1 = O[dt][1] * li0;
            size_t off = (size_t)(b * T_ + r0) * C_ + h * DH_ + d;
            __nv_bfloat16 h0 = __float2bfloat16(v0), h1 = __float2bfloat16(v1);
            float lo0 = v0 - __bfloat162float(h0), lo1 = v1 - __bfloat162float(h1);
            uint16_t u0, u1; memcpy(&u0, &h0, 2); memcpy(&u1, &h1, 2);
            *(uint32_t*)(g_yh + off) = (uint32_t)u0 | ((uint32_t)u1 << 16);
            *(uint32_t*)(g_yl + off) = cvt_bf16x2(lo1, lo0);
        }
        {
            float v0 = O[dt][2] * li1, v1 = O[dt][3] * li1;
            size_t off = (size_t)(b * T_ + r0 + 8) * C_ + h * DH_ + d;
            __nv_bfloat16 h0 = __float2bfloat16(v0), h1 = __float2bfloat16(v1);
            float lo0 = v0 - __bfloat162float(h0), lo1 = v1 - __bfloat162float(h1);
            uint16_t u0, u1; memcpy(&u0, &h0, 2); memcpy(&u1, &h1, 2);
            *(uint32_t*)(g_yh + off) = (uint32_t)u0 | ((uint32_t)u1 << 16);
            *(uint32_t*)(g_yl + off) = cvt_bf16x2(lo1, lo0);
        }
    }
}

// ---------------------------------------------------------------------------
extern "C" void kernel_launch(void* const* d_in, const int* in_sizes, int n_in,
                              void* d_out, int out_size)
{
    const float* x      = (const float*)d_in[0];
    const float* w_qkv  = (const float*)d_in[1];
    const float* w_proj = (const float*)d_in[2];
    float* out = (float*)d_out;
    (void)in_sizes; (void)n_in; (void)out_size;

    cudaFuncSetAttribute(mma_gemm_kernel,
                         cudaFuncAttributeMaxDynamicSharedMemorySize, SM_GEMM_TOTAL);
    cudaFuncSetAttribute(attn_mma_kernel,
                         cudaFuncAttributeMaxDynamicSharedMemorySize, AS_TOTAL);

    __nv_bfloat16 *xh, *xl, *yh, *yl, *wqh, *wql, *wph, *wpl;
    cudaGetSymbolAddress((void**)&xh,  g_xh);
    cudaGetSymbolAddress((void**)&xl,  g_xl);
    cudaGetSymbolAddress((void**)&yh,  g_yh);
    cudaGetSymbolAddress((void**)&yl,  g_yl);
    cudaGetSymbolAddress((void**)&wqh, g_wqkvTh);
    cudaGetSymbolAddress((void**)&wql, g_wqkvTl);
    cudaGetSymbolAddress((void**)&wph, g_wprojTh);
    cudaGetSymbolAddress((void**)&wpl, g_wprojTl);

    // prep
    convert_x_kernel<<<M_ * K_ / (256 * 4), 256>>>(x);
    transpose_w_kernel<<<dim3(N_QKV / 32, K_ / 32), dim3(32, 8)>>>(w_qkv, wqh, wql, N_QKV);
    transpose_w_kernel<<<dim3(C_ / 32, K_ / 32), dim3(32, 8)>>>(w_proj, wph, wpl, C_);

    // QKV GEMM with fused hi/lo split-scatter + q scale
    mma_gemm_kernel<<<dim3(N_QKV / 64, M_ / 128), 256, SM_GEMM_TOTAL>>>(
        xh, xl, wqh, wql, nullptr, 0);

    // tensor-core causal flash attention (bh fastest, qt descending)
    attn_mma_kernel<<<dim3(B_ * H_, T_ / 128), 256, AS_TOTAL>>>();

    // output projection GEMM
    mma_gemm_kernel<<<dim3(C_ / 64, M_ / 128), 256, SM_GEMM_TOTAL>>>(
        yh, yl, wph, wpl, out, 1);
}

// round 9
// speedup vs baseline: 1.6622x; 1.3773x over previous
#include <cuda_runtime.h>
#include <cuda_fp16.h>
#include <cstdint>
#include <cstring>

// Problem constants
#define B_   4
#define T_   2048
#define C_   1024
#define H_   16
#define DH_  64
#define M_   (B_ * T_)          // 8192
#define N_QKV (3 * C_)          // 3072
#define K_   1024

// ---------------------------------------------------------------------------
// Device-global scratch
// ---------------------------------------------------------------------------
__device__ __half g_qh[B_ * H_ * T_ * DH_];
__device__ __half g_ql[B_ * H_ * T_ * DH_];
__device__ __half g_kh[B_ * H_ * T_ * DH_];
__device__ __half g_vh[B_ * H_ * T_ * DH_];
__device__ __half g_xh[M_ * K_];
__device__ __half g_xl[M_ * K_];
__device__ __half g_yh[M_ * C_];
__device__ __half g_yl[M_ * C_];
__device__ __half g_wqkvT[N_QKV * K_];   // [N][K]
__device__ __half g_wprojT[C_ * K_];

#define SMEM_SWIZZLE_128B(o) ((o) ^ (((o) >> 3) & 0x70))

__device__ __forceinline__ uint32_t smem_to_u32(const void* p) {
    uint32_t a;
    asm("{ .reg .u64 t; cvta.to.shared.u64 t, %1; cvt.u32.u64 %0, t; }" : "=r"(a) : "l"(p));
    return a;
}
__device__ __forceinline__ void cp16(uint32_t saddr, const void* g) {
    asm volatile("cp.async.cg.shared.global [%0], [%1], 16;" :: "r"(saddr), "l"(g));
}
__device__ __forceinline__ void cp_commit() {
    asm volatile("cp.async.commit_group;" ::: "memory");
}
__device__ __forceinline__ void ldsm_x4(uint32_t* r, uint32_t addr) {
    asm volatile("ldmatrix.sync.aligned.m8n8.x4.shared.b16 {%0,%1,%2,%3}, [%4];"
        : "=r"(r[0]), "=r"(r[1]), "=r"(r[2]), "=r"(r[3]) : "r"(addr));
}
__device__ __forceinline__ void ldsm_x4_trans(uint32_t* r, uint32_t addr) {
    asm volatile("ldmatrix.sync.aligned.m8n8.x4.trans.shared.b16 {%0,%1,%2,%3}, [%4];"
        : "=r"(r[0]), "=r"(r[1]), "=r"(r[2]), "=r"(r[3]) : "r"(addr));
}
__device__ __forceinline__ void mma_f16(float* c, const uint32_t* a, const uint32_t* b) {
    asm volatile("mma.sync.aligned.m16n8k16.row.col.f32.f16.f16.f32 "
        "{%0,%1,%2,%3}, {%4,%5,%6,%7}, {%8,%9}, {%0,%1,%2,%3};"
        : "+f"(c[0]), "+f"(c[1]), "+f"(c[2]), "+f"(c[3])
        : "r"(a[0]), "r"(a[1]), "r"(a[2]), "r"(a[3]), "r"(b[0]), "r"(b[1]));
}
__device__ __forceinline__ uint32_t pack_h2(float lo, float hi) {
    __half2 h = __floats2half2_rn(lo, hi);   // x = lo bits
    uint32_t u; memcpy(&u, &h, 4); return u;
}
__device__ __forceinline__ float2 unpack_h2(uint32_t u) {
    __half2 h; memcpy(&h, &u, 4);
    return __half22float2(h);
}

// ---------------------------------------------------------------------------
// Prep: split x (fp32) into fp16 hi/lo
// ---------------------------------------------------------------------------
__global__ __launch_bounds__(256) void convert_x_kernel(const float* __restrict__ x)
{
    int idx = (blockIdx.x * 256 + threadIdx.x) * 4;
    float4 v = *(const float4*)(x + idx);
    float vv[4] = {v.x, v.y, v.z, v.w};
    __half h[4], l[4];
#pragma unroll
    for (int i = 0; i < 4; i++) {
        h[i] = __float2half_rn(vv[i]);
        l[i] = __float2half_rn(vv[i] - __half2float(h[i]));
    }
    *(uint2*)(g_xh + idx) = *(uint2*)h;
    *(uint2*)(g_xl + idx) = *(uint2*)l;
}

// ---------------------------------------------------------------------------
// Prep: transpose W [K,N] -> WT [N,K] fp16 (single, RN)
// ---------------------------------------------------------------------------
__global__ __launch_bounds__(256) void transpose_w_kernel(
    const float* __restrict__ W, __half* __restrict__ WT, int N)
{
    __shared__ float t[32][33];
    int n0 = blockIdx.x * 32, k0 = blockIdx.y * 32;
    int tx = threadIdx.x, ty = threadIdx.y;
#pragma unroll
    for (int i = 0; i < 4; i++)
        t[ty + i * 8][tx] = W[(size_t)(k0 + ty + i * 8) * N + n0 + tx];
    __syncthreads();
#pragma unroll
    for (int i = 0; i < 4; i++) {
        int n = n0 + ty + i * 8;
        int k = k0 + tx;
        WT[(size_t)n * K_ + k] = __float2half_rn(t[tx][ty + i * 8]);
    }
}

// ---------------------------------------------------------------------------
// Tensor-core GEMM, 2-term fp16: C = (Ah+Al) @ B^T, B pre-rounded fp16.
// CTA tile 128(M)x64(N), BK=64, 256 threads / 8 warps (4m x 2n), wtile 32x32.
// Stage 40KB (Ah16|Al16|B8), double-buffered 80KB -> 2 CTAs/SM.
// mode 0: scatter q (fp16 hi/lo, scaled) / k,v (fp16); mode 1: f32 store.
// ---------------------------------------------------------------------------
#define STAGE_BYTES 40960
#define SM_GEMM_TOTAL (2 * STAGE_BYTES)   // 81920

__global__ __launch_bounds__(256, 2) void mma_gemm_kernel(
    const __half* __restrict__ Ah, const __half* __restrict__ Al,
    const __half* __restrict__ Bm,
    float* __restrict__ out, int mode)
{
    extern __shared__ char smem[];
    uint32_t sbase = smem_to_u32(smem);

    int tid = threadIdx.x;
    int wid = tid >> 5;
    int lane = tid & 31;
    int wm = wid >> 1;          // 0..3
    int wn = wid & 1;           // 0..1

    int m0 = blockIdx.y * 128;
    int n0 = blockIdx.x * 64;

    float acc[2][4][4];
#pragma unroll
    for (int i = 0; i < 2; i++)
#pragma unroll
        for (int j = 0; j < 4; j++)
#pragma unroll
            for (int c = 0; c < 4; c++) acc[i][j][c] = 0.f;

    auto load_chunk = [&](int kt, int s) {
        uint32_t st = sbase + s * STAGE_BYTES;
#pragma unroll
        for (int p = 0; p < 4; p++) {
            int idx = tid + p * 256;
            int row = idx >> 3;
            int ch  = idx & 7;
            uint32_t so = SMEM_SWIZZLE_128B(row * 128 + ch * 16);
            size_t ka = (size_t)(m0 + row) * K_ + kt * 64 + ch * 8;
            cp16(st + so,         Ah + ka);
            cp16(st + 16384 + so, Al + ka);
        }
#pragma unroll
        for (int p = 0; p < 2; p++) {
            int idx = tid + p * 256;
            int row = idx >> 3;
            int ch  = idx & 7;
            uint32_t so = SMEM_SWIZZLE_128B(row * 128 + ch * 16);
            size_t kb = (size_t)(n0 + row) * K_ + kt * 64 + ch * 8;
            cp16(st + 32768 + so, Bm + kb);
        }
        cp_commit();
    };

    load_chunk(0, 0);

    int a_row = lane & 15;
    int a_cb  = (lane >> 4) << 4;
    int bg     = lane >> 3;
    int bp_row = (lane & 7) + ((bg >> 1) << 3);
    int bp_cb  = (bg & 1) << 4;

    for (int kt = 0; kt < 16; kt++) {
        int s = kt & 1;
        if (kt + 1 < 16) {
            load_chunk(kt + 1, (kt + 1) & 1);
            asm volatile("cp.async.wait_group 1;" ::: "memory");
        } else {
            asm volatile("cp.async.wait_group 0;" ::: "memory");
        }
        __syncthreads();

        uint32_t sAh = sbase + s * STAGE_BYTES;
        uint32_t sAl = sAh + 16384;
        uint32_t sB  = sAh + 32768;

#pragma unroll
        for (int ks = 0; ks < 4; ks++) {
            int kB = ks * 32;
            uint32_t ah[2][4], al[2][4], bh[4][2];
#pragma unroll
            for (int i = 0; i < 2; i++) {
                uint32_t off = SMEM_SWIZZLE_128B((wm * 32 + i * 16 + a_row) * 128 + kB + a_cb);
                ldsm_x4(ah[i], sAh + off);
                ldsm_x4(al[i], sAl + off);
            }
#pragma unroll
            for (int jp = 0; jp < 2; jp++) {
                uint32_t off = SMEM_SWIZZLE_128B((wn * 32 + jp * 16 + bp_row) * 128 + kB + bp_cb);
                uint32_t r4[4];
                ldsm_x4(r4, sB + off);
                bh[2 * jp][0] = r4[0]; bh[2 * jp][1] = r4[1];
                bh[2 * jp + 1][0] = r4[2]; bh[2 * jp + 1][1] = r4[3];
            }
#pragma unroll
            for (int i = 0; i < 2; i++)
#pragma unroll
                for (int j = 0; j < 4; j++) mma_f16(acc[i][j], ah[i], bh[j]);
#pragma unroll
            for (int i = 0; i < 2; i++)
#pragma unroll
                for (int j = 0; j < 4; j++) mma_f16(acc[i][j], al[i], bh[j]);
        }
        __syncthreads();
    }

    int r4i = lane >> 2;
    int cp2 = (lane & 3) * 2;

    if (mode == 1) {
#pragma unroll
        for (int i = 0; i < 2; i++)
#pragma unroll
            for (int j = 0; j < 4; j++) {
                int n = n0 + wn * 32 + j * 8 + cp2;
#pragma unroll
                for (int rr = 0; rr < 2; rr++) {
                    int m = m0 + wm * 32 + i * 16 + r4i + rr * 8;
                    *(float2*)(out + (size_t)m * C_ + n) =
                        make_float2(acc[i][j][rr * 2], acc[i][j][rr * 2 + 1]);
                }
            }
    } else {
        int which = n0 >> 10;
#pragma unroll
        for (int i = 0; i < 2; i++)
#pragma unroll
            for (int j = 0; j < 4; j++) {
                int n = n0 + wn * 32 + j * 8 + cp2;
                int h = (n & 1023) >> 6;
                int d = n & 63;
#pragma unroll
                for (int rr = 0; rr < 2; rr++) {
                    int m = m0 + wm * 32 + i * 16 + r4i + rr * 8;
                    int b = m >> 11;
                    int t = m & 2047;
                    size_t off = (size_t)(((b << 4) + h) * T_ + t) * DH_ + d;
                    float v0 = acc[i][j][rr * 2];
                    float v1 = acc[i][j][rr * 2 + 1];
                    if (which == 0) {           // Q: scale + hi/lo split
                        v0 *= 0.125f; v1 *= 0.125f;
                        uint32_t hp = pack_h2(v0, v1);
                        float2 bk = unpack_h2(hp);
                        *(uint32_t*)(g_qh + off) = hp;
                        *(uint32_t*)(g_ql + off) = pack_h2(v0 - bk.x, v1 - bk.y);
                    } else if (which == 1) {    // K: single fp16
                        *(uint32_t*)(g_kh + off) = pack_h2(v0, v1);
                    } else {                    // V: single fp16
                        *(uint32_t*)(g_vh + off) = pack_h2(v0, v1);
                    }
                }
            }
    }
}

// ---------------------------------------------------------------------------
// Tensor-core causal flash attention, 2-term fp16.
// Q split hi/lo (A-side), K/V single fp16 (B-side). 2 CTAs/SM, LPT grid.
// ---------------------------------------------------------------------------
#define AS_QH 0
#define AS_QL 16384
#define AS_KV 32768           // + stage*16384 : Kh(8K) | Vh(8K)
#define AS_TOTAL (32768 + 2 * 16384)   // 65536

__global__ __launch_bounds__(256, 2) void attn_mma_kernel()
{
    extern __shared__ char smem[];
    uint32_t sb = smem_to_u32(smem);
    int tid = threadIdx.x;
    int wid = tid >> 5;
    int lane = tid & 31;

    int qt = 15 - blockIdx.y;     // longest first
    int bh = blockIdx.x;
    int q0 = qt * 128;
    size_t base = (size_t)bh * T_ * DH_;
    int nkt = 2 * qt + 2;

#pragma unroll
    for (int p = 0; p < 4; p++) {
        int idx = tid + p * 256;
        int row = idx >> 3;
        int ch  = idx & 7;
        uint32_t so = SMEM_SWIZZLE_128B(row * 128 + ch * 16);
        size_t g = base + (size_t)(q0 + row) * DH_ + ch * 8;
        cp16(sb + AS_QH + so, g_qh + g);
        cp16(sb + AS_QL + so, g_ql + g);
    }
    cp_commit();

    auto load_kv = [&](int j, int s) {
        uint32_t st = sb + AS_KV + s * 16384;
#pragma unroll
        for (int p = 0; p < 2; p++) {
            int idx = tid + p * 256;
            int row = idx >> 3;
            int ch  = idx & 7;
            uint32_t so = SMEM_SWIZZLE_128B(row * 128 + ch * 16);
            size_t g = base + (size_t)(j * 64 + row) * DH_ + ch * 8;
            cp16(st + so,        g_kh + g);
            cp16(st + 8192 + so, g_vh + g);
        }
        cp_commit();
    };

    load_kv(0, 0);

    uint32_t qh[4][4], ql[4][4];
    float O[8][4];
#pragma unroll
    for (int dt = 0; dt < 8; dt++)
#pragma unroll
        for (int c = 0; c < 4; c++) O[dt][c] = 0.f;
    float m0r = -1e30f, m1r = -1e30f, l0r = 0.f, l1r = 0.f;

    int g4 = lane >> 2;
    int c2 = 2 * (lane & 3);
    int a_row = lane & 15;
    int a_cb  = (lane >> 4) << 4;
    int bg     = lane >> 3;
    int bp_row = (lane & 7) + ((bg >> 1) << 3);
    int bp_cb  = (bg & 1) << 4;
    // V trans-pair addressing: lanes 0-15 -> tile dt0 (k-lo/k-hi rows),
    // lanes 16-31 -> tile dt1
    int v_row = (lane & 7) + ((lane >> 3) & 1) * 8;
    int v_ct  = (lane >> 4) & 1;

    for (int j = 0; j < nkt; j++) {
        int s = j & 1;
        if (j + 1 < nkt) {
            load_kv(j + 1, (j + 1) & 1);
            asm volatile("cp.async.wait_group 1;" ::: "memory");
        } else {
            asm volatile("cp.async.wait_group 0;" ::: "memory");
        }
        __syncthreads();

        if (j == 0) {
#pragma unroll
            for (int ks = 0; ks < 4; ks++) {
                uint32_t off = SMEM_SWIZZLE_128B((wid * 16 + a_row) * 128 + ks * 32 + a_cb);
                ldsm_x4(qh[ks], sb + AS_QH + off);
                ldsm_x4(ql[ks], sb + AS_QL + off);
            }
        }

        uint32_t stK = sb + AS_KV + s * 16384;
        uint32_t stV = stK + 8192;

        // ---- S = Q @ K^T (2-term, paired-K ldsm) ----
        float S[8][4];
#pragma unroll
        for (int jt = 0; jt < 8; jt++)
#pragma unroll
            for (int c = 0; c < 4; c++) S[jt][c] = 0.f;

#pragma unroll
        for (int jp = 0; jp < 4; jp++) {
#pragma unroll
            for (int ks = 0; ks < 4; ks++) {
                uint32_t off = SMEM_SWIZZLE_128B((jp * 16 + bp_row) * 128 + ks * 32 + bp_cb);
                uint32_t r4[4];
                ldsm_x4(r4, stK + off);
                mma_f16(S[2 * jp],     qh[ks], r4);
                mma_f16(S[2 * jp],     ql[ks], r4);
                mma_f16(S[2 * jp + 1], qh[ks], r4 + 2);
                mma_f16(S[2 * jp + 1], ql[ks], r4 + 2);
            }
        }

        if (j >= 2 * qt) {
            int r0 = q0 + wid * 16 + g4;
            int cb = j * 64 + c2;
#pragma unroll
            for (int jt = 0; jt < 8; jt++) {
                int c0 = cb + jt * 8;
                if (c0 > r0)     S[jt][0] = -1e30f;
                if (c0 + 1 > r0) S[jt][1] = -1e30f;
                if (c0 > r0 + 8)     S[jt][2] = -1e30f;
                if (c0 + 1 > r0 + 8) S[jt][3] = -1e30f;
            }
        }

        float mx0 = -1e30f, mx1 = -1e30f;
#pragma unroll
        for (int jt = 0; jt < 8; jt++) {
            mx0 = fmaxf(mx0, fmaxf(S[jt][0], S[jt][1]));
            mx1 = fmaxf(mx1, fmaxf(S[jt][2], S[jt][3]));
        }
        mx0 = fmaxf(mx0, __shfl_xor_sync(0xffffffffu, mx0, 1));
        mx0 = fmaxf(mx0, __shfl_xor_sync(0xffffffffu, mx0, 2));
        mx1 = fmaxf(mx1, __shfl_xor_sync(0xffffffffu, mx1, 1));
        mx1 = fmaxf(mx1, __shfl_xor_sync(0xffffffffu, mx1, 2));

        float mn0 = fmaxf(m0r, mx0), mn1 = fmaxf(m1r, mx1);
        float al0 = __expf(m0r - mn0), al1 = __expf(m1r - mn1);
        m0r = mn0; m1r = mn1;

        float s0 = 0.f, s1 = 0.f;
#pragma unroll
        for (int jt = 0; jt < 8; jt++) {
            S[jt][0] = __expf(S[jt][0] - mn0); s0 += S[jt][0];
            S[jt][1] = __expf(S[jt][1] - mn0); s0 += S[jt][1];
            S[jt][2] = __expf(S[jt][2] - mn1); s1 += S[jt][2];
            S[jt][3] = __expf(S[jt][3] - mn1); s1 += S[jt][3];
        }
        s0 += __shfl_xor_sync(0xffffffffu, s0, 1);
        s0 += __shfl_xor_sync(0xffffffffu, s0, 2);
        s1 += __shfl_xor_sync(0xffffffffu, s1, 1);
        s1 += __shfl_xor_sync(0xffffffffu, s1, 2);
        l0r = l0r * al0 + s0;
        l1r = l1r * al1 + s1;

#pragma unroll
        for (int dt = 0; dt < 8; dt++) {
            O[dt][0] *= al0; O[dt][1] *= al0;
            O[dt][2] *= al1; O[dt][3] *= al1;
        }

        // ---- pack P hi/lo IN PLACE (fp16): S[t][cb]=hi bits, [cb+1]=lo bits
#pragma unroll
        for (int ks2 = 0; ks2 < 4; ks2++) {
#pragma unroll
            for (int q = 0; q < 4; q++) {
                int tile = 2 * ks2 + (q >> 1);
                int cb = (q & 1) * 2;
                float p0 = S[tile][cb], p1 = S[tile][cb + 1];
                uint32_t hp = pack_h2(p0, p1);
                float2 bk = unpack_h2(hp);
                S[tile][cb]     = __uint_as_float(hp);
                S[tile][cb + 1] = __uint_as_float(pack_h2(p0 - bk.x, p1 - bk.y));
            }
        }

        // ---- O += P @ V (2-term, paired-trans ldsm over dt pairs) ----
#pragma unroll
        for (int dtp = 0; dtp < 4; dtp++) {
#pragma unroll
            for (int ks2 = 0; ks2 < 4; ks2++) {
                uint32_t ph[4] = {
                    __float_as_uint(S[2 * ks2][0]),     __float_as_uint(S[2 * ks2][2]),
                    __float_as_uint(S[2 * ks2 + 1][0]), __float_as_uint(S[2 * ks2 + 1][2])};
                uint32_t pl[4] = {
                    __float_as_uint(S[2 * ks2][1]),     __float_as_uint(S[2 * ks2][3]),
                    __float_as_uint(S[2 * ks2 + 1][1]), __float_as_uint(S[2 * ks2 + 1][3])};
                uint32_t off = SMEM_SWIZZLE_128B((ks2 * 16 + v_row) * 128 +
                                                 (2 * dtp + v_ct) * 16);
                uint32_t r4[4];
                ldsm_x4_trans(r4, stV + off);
                mma_f16(O[2 * dtp],     ph, r4);
                mma_f16(O[2 * dtp],     pl, r4);
                mma_f16(O[2 * dtp + 1], ph, r4 + 2);
                mma_f16(O[2 * dtp + 1], pl, r4 + 2);
            }
        }
        __syncthreads();
    }

    // ---- epilogue: y = O / l, fp16 hi/lo split ----
    float li0 = 1.f / l0r, li1 = 1.f / l1r;
    int b = bh >> 4, h = bh & 15;
    int r0 = q0 + wid * 16 + g4;
#pragma unroll
    for (int dt = 0; dt < 8; dt++) {
        int d = dt * 8 + c2;
        {
            float v0 = O[dt][0] * li0, v1 = O[dt][1] * li0;
            size_t off = (size_t)(b * T_ + r0) * C_ + h * DH_ + d;
            uint32_t hp = pack_h2(v0, v1);
            float2 bk = unpack_h2(hp);
            *(uint32_t*)(g_yh + off) = hp;
            *(uint32_t*)(g_yl + off) = pack_h2(v0 - bk.x, v1 - bk.y);
        }
        {
            float v0 = O[dt][2] * li1, v1 = O[dt][3] * li1;
            size_t off = (size_t)(b * T_ + r0 + 8) * C_ + h * DH_ + d;
            uint32_t hp = pack_h2(v0, v1);
            float2 bk = unpack_h2(hp);
            *(uint32_t*)(g_yh + off) = hp;
            *(uint32_t*)(g_yl + off) = pack_h2(v0 - bk.x, v1 - bk.y);
        }
    }
}

// ---------------------------------------------------------------------------
extern "C" void kernel_launch(void* const* d_in, const int* in_sizes, int n_in,
                              void* d_out, int out_size)
{
    const float* x      = (const float*)d_in[0];
    const float* w_qkv  = (const float*)d_in[1];
    const float* w_proj = (const float*)d_in[2];
    float* out = (float*)d_out;
    (void)in_sizes; (void)n_in; (void)out_size;

    cudaFuncSetAttribute(mma_gemm_kernel,
                         cudaFuncAttributeMaxDynamicSharedMemorySize, SM_GEMM_TOTAL);
    cudaFuncSetAttribute(attn_mma_kernel,
                         cudaFuncAttributeMaxDynamicSharedMemorySize, AS_TOTAL);

    __half *xh, *xl, *yh, *yl, *wq, *wp;
    cudaGetSymbolAddress((void**)&xh, g_xh);
    cudaGetSymbolAddress((void**)&xl, g_xl);
    cudaGetSymbolAddress((void**)&yh, g_yh);
    cudaGetSymbolAddress((void**)&yl, g_yl);
    cudaGetSymbolAddress((void**)&wq, g_wqkvT);
    cudaGetSymbolAddress((void**)&wp, g_wprojT);

    // prep
    convert_x_kernel<<<M_ * K_ / (256 * 4), 256>>>(x);
    transpose_w_kernel<<<dim3(N_QKV / 32, K_ / 32), dim3(32, 8)>>>(w_qkv, wq, N_QKV);
    transpose_w_kernel<<<dim3(C_ / 32, K_ / 32), dim3(32, 8)>>>(w_proj, wp, C_);

    // QKV GEMM with fused q-split/scale + k/v fp16 scatter
    mma_gemm_kernel<<<dim3(N_QKV / 64, M_ / 128), 256, SM_GEMM_TOTAL>>>(
        xh, xl, wq, nullptr, 0);

    // tensor-core causal flash attention (bh fastest, qt descending)
    attn_mma_kernel<<<dim3(B_ * H_, T_ / 128), 256, AS_TOTAL>>>();

    // output projection GEMM
    mma_gemm_kernel<<<dim3(C_ / 64, M_ / 128), 256, SM_GEMM_TOTAL>>>(
        yh, yl, wp, out, 1);
}

// round 10
// speedup vs baseline: 2.2398x; 1.3475x over previous
#include <cuda_runtime.h>
#include <cuda_fp16.h>
#include <cstdint>
#include <cstring>

// Problem constants
#define B_   4
#define T_   2048
#define C_   1024
#define H_   16
#define DH_  64
#define M_   (B_ * T_)          // 8192
#define N_QKV (3 * C_)          // 3072
#define K_   1024

// ---------------------------------------------------------------------------
// Device-global scratch
// ---------------------------------------------------------------------------
__device__ __half g_qh[B_ * H_ * T_ * DH_];
__device__ __half g_ql[B_ * H_ * T_ * DH_];
__device__ __half g_kh[B_ * H_ * T_ * DH_];
__device__ __half g_vh[B_ * H_ * T_ * DH_];
__device__ __half g_xh[M_ * K_];
__device__ __half g_yh[M_ * C_];
__device__ __half g_wqkvT[N_QKV * K_];   // [N][K]
__device__ __half g_wprojT[C_ * K_];

#define SMEM_SWIZZLE_128B(o) ((o) ^ (((o) >> 3) & 0x70))

__device__ __forceinline__ uint32_t smem_to_u32(const void* p) {
    uint32_t a;
    asm("{ .reg .u64 t; cvta.to.shared.u64 t, %1; cvt.u32.u64 %0, t; }" : "=r"(a) : "l"(p));
    return a;
}
__device__ __forceinline__ void cp16(uint32_t saddr, const void* g) {
    asm volatile("cp.async.cg.shared.global [%0], [%1], 16;" :: "r"(saddr), "l"(g));
}
__device__ __forceinline__ void cp_commit() {
    asm volatile("cp.async.commit_group;" ::: "memory");
}
__device__ __forceinline__ void ldsm_x4(uint32_t* r, uint32_t addr) {
    asm volatile("ldmatrix.sync.aligned.m8n8.x4.shared.b16 {%0,%1,%2,%3}, [%4];"
        : "=r"(r[0]), "=r"(r[1]), "=r"(r[2]), "=r"(r[3]) : "r"(addr));
}
__device__ __forceinline__ void ldsm_x4_trans(uint32_t* r, uint32_t addr) {
    asm volatile("ldmatrix.sync.aligned.m8n8.x4.trans.shared.b16 {%0,%1,%2,%3}, [%4];"
        : "=r"(r[0]), "=r"(r[1]), "=r"(r[2]), "=r"(r[3]) : "r"(addr));
}
__device__ __forceinline__ void mma_f16(float* c, const uint32_t* a, const uint32_t* b) {
    asm volatile("mma.sync.aligned.m16n8k16.row.col.f32.f16.f16.f32 "
        "{%0,%1,%2,%3}, {%4,%5,%6,%7}, {%8,%9}, {%0,%1,%2,%3};"
        : "+f"(c[0]), "+f"(c[1]), "+f"(c[2]), "+f"(c[3])
        : "r"(a[0]), "r"(a[1]), "r"(a[2]), "r"(a[3]), "r"(b[0]), "r"(b[1]));
}
__device__ __forceinline__ uint32_t pack_h2(float lo, float hi) {
    __half2 h = __floats2half2_rn(lo, hi);
    uint32_t u; memcpy(&u, &h, 4); return u;
}
__device__ __forceinline__ float2 unpack_h2(uint32_t u) {
    __half2 h; memcpy(&h, &u, 4);
    return __half22float2(h);
}

// ---------------------------------------------------------------------------
// Prep: round x (fp32) to fp16
// ---------------------------------------------------------------------------
__global__ __launch_bounds__(256) void convert_x_kernel(const float* __restrict__ x)
{
    int idx = (blockIdx.x * 256 + threadIdx.x) * 4;
    float4 v = *(const float4*)(x + idx);
    float vv[4] = {v.x, v.y, v.z, v.w};
    __half h[4];
#pragma unroll
    for (int i = 0; i < 4; i++) h[i] = __float2half_rn(vv[i]);
    *(uint2*)(g_xh + idx) = *(uint2*)h;
}

// ---------------------------------------------------------------------------
// Prep: transpose W [K,N] -> WT [N,K] fp16
// ---------------------------------------------------------------------------
__global__ __launch_bounds__(256) void transpose_w_kernel(
    const float* __restrict__ W, __half* __restrict__ WT, int N)
{
    __shared__ float t[32][33];
    int n0 = blockIdx.x * 32, k0 = blockIdx.y * 32;
    int tx = threadIdx.x, ty = threadIdx.y;
#pragma unroll
    for (int i = 0; i < 4; i++)
        t[ty + i * 8][tx] = W[(size_t)(k0 + ty + i * 8) * N + n0 + tx];
    __syncthreads();
#pragma unroll
    for (int i = 0; i < 4; i++) {
        int n = n0 + ty + i * 8;
        int k = k0 + tx;
        WT[(size_t)n * K_ + k] = __float2half_rn(t[tx][ty + i * 8]);
    }
}

// ---------------------------------------------------------------------------
// Tensor-core GEMM, 1-term fp16: C = A @ B^T, both operands fp16.
// CTA tile 128(M)x64(N), BK=64, 256 threads / 8 warps (4m x 2n), wtile 32x32.
// Stage 24KB (A16|B8), double-buffered 48KB -> 3 CTAs/SM (regs capped 85).
// mode 0: scatter q (fp16 hi/lo, scaled) / k,v (fp16); mode 1: f32 store.
// ---------------------------------------------------------------------------
#define STAGE_BYTES 24576
#define SM_GEMM_TOTAL (2 * STAGE_BYTES)   // 49152

__global__ __launch_bounds__(256, 3) void mma_gemm_kernel(
    const __half* __restrict__ Ah, const __half* __restrict__ Bm,
    float* __restrict__ out, int mode)
{
    extern __shared__ char smem[];
    uint32_t sbase = smem_to_u32(smem);

    int tid = threadIdx.x;
    int wid = tid >> 5;
    int lane = tid & 31;
    int wm = wid >> 1;          // 0..3
    int wn = wid & 1;           // 0..1

    int m0 = blockIdx.y * 128;
    int n0 = blockIdx.x * 64;

    float acc[2][4][4];
#pragma unroll
    for (int i = 0; i < 2; i++)
#pragma unroll
        for (int j = 0; j < 4; j++)
#pragma unroll
            for (int c = 0; c < 4; c++) acc[i][j][c] = 0.f;

    auto load_chunk = [&](int kt, int s) {
        uint32_t st = sbase + s * STAGE_BYTES;
#pragma unroll
        for (int p = 0; p < 4; p++) {
            int idx = tid + p * 256;
            int row = idx >> 3;
            int ch  = idx & 7;
            uint32_t so = SMEM_SWIZZLE_128B(row * 128 + ch * 16);
            size_t ka = (size_t)(m0 + row) * K_ + kt * 64 + ch * 8;
            cp16(st + so, Ah + ka);
        }
#pragma unroll
        for (int p = 0; p < 2; p++) {
            int idx = tid + p * 256;
            int row = idx >> 3;
            int ch  = idx & 7;
            uint32_t so = SMEM_SWIZZLE_128B(row * 128 + ch * 16);
            size_t kb = (size_t)(n0 + row) * K_ + kt * 64 + ch * 8;
            cp16(st + 16384 + so, Bm + kb);
        }
        cp_commit();
    };

    load_chunk(0, 0);

    int a_row = lane & 15;
    int a_cb  = (lane >> 4) << 4;
    int bg     = lane >> 3;
    int bp_row = (lane & 7) + ((bg >> 1) << 3);
    int bp_cb  = (bg & 1) << 4;

    for (int kt = 0; kt < 16; kt++) {
        int s = kt & 1;
        if (kt + 1 < 16) {
            load_chunk(kt + 1, (kt + 1) & 1);
            asm volatile("cp.async.wait_group 1;" ::: "memory");
        } else {
            asm volatile("cp.async.wait_group 0;" ::: "memory");
        }
        __syncthreads();

        uint32_t sA = sbase + s * STAGE_BYTES;
        uint32_t sB = sA + 16384;

#pragma unroll
        for (int ks = 0; ks < 4; ks++) {
            int kB = ks * 32;
            uint32_t ah[2][4], bh[4][2];
#pragma unroll
            for (int i = 0; i < 2; i++) {
                uint32_t off = SMEM_SWIZZLE_128B((wm * 32 + i * 16 + a_row) * 128 + kB + a_cb);
                ldsm_x4(ah[i], sA + off);
            }
#pragma unroll
            for (int jp = 0; jp < 2; jp++) {
                uint32_t off = SMEM_SWIZZLE_128B((wn * 32 + jp * 16 + bp_row) * 128 + kB + bp_cb);
                uint32_t r4[4];
                ldsm_x4(r4, sB + off);
                bh[2 * jp][0] = r4[0]; bh[2 * jp][1] = r4[1];
                bh[2 * jp + 1][0] = r4[2]; bh[2 * jp + 1][1] = r4[3];
            }
#pragma unroll
            for (int i = 0; i < 2; i++)
#pragma unroll
                for (int j = 0; j < 4; j++) mma_f16(acc[i][j], ah[i], bh[j]);
        }
        __syncthreads();
    }

    int r4i = lane >> 2;
    int cp2 = (lane & 3) * 2;

    if (mode == 1) {
#pragma unroll
        for (int i = 0; i < 2; i++)
#pragma unroll
            for (int j = 0; j < 4; j++) {
                int n = n0 + wn * 32 + j * 8 + cp2;
#pragma unroll
                for (int rr = 0; rr < 2; rr++) {
                    int m = m0 + wm * 32 + i * 16 + r4i + rr * 8;
                    *(float2*)(out + (size_t)m * C_ + n) =
                        make_float2(acc[i][j][rr * 2], acc[i][j][rr * 2 + 1]);
                }
            }
    } else {
        int which = n0 >> 10;
#pragma unroll
        for (int i = 0; i < 2; i++)
#pragma unroll
            for (int j = 0; j < 4; j++) {
                int n = n0 + wn * 32 + j * 8 + cp2;
                int h = (n & 1023) >> 6;
                int d = n & 63;
#pragma unroll
                for (int rr = 0; rr < 2; rr++) {
                    int m = m0 + wm * 32 + i * 16 + r4i + rr * 8;
                    int b = m >> 11;
                    int t = m & 2047;
                    size_t off = (size_t)(((b << 4) + h) * T_ + t) * DH_ + d;
                    float v0 = acc[i][j][rr * 2];
                    float v1 = acc[i][j][rr * 2 + 1];
                    if (which == 0) {           // Q: scale + hi/lo split
                        v0 *= 0.125f; v1 *= 0.125f;
                        uint32_t hp = pack_h2(v0, v1);
                        float2 bk = unpack_h2(hp);
                        *(uint32_t*)(g_qh + off) = hp;
                        *(uint32_t*)(g_ql + off) = pack_h2(v0 - bk.x, v1 - bk.y);
                    } else if (which == 1) {    // K: single fp16
                        *(uint32_t*)(g_kh + off) = pack_h2(v0, v1);
                    } else {                    // V: single fp16
                        *(uint32_t*)(g_vh + off) = pack_h2(v0, v1);
                    }
                }
            }
    }
}

// ---------------------------------------------------------------------------
// Tensor-core causal flash attention, 2-term fp16 (Q/P split, K/V single).
// 2 CTAs/SM, LPT grid. Epilogue writes y single fp16 (proj is 1-term).
// ---------------------------------------------------------------------------
#define AS_QH 0
#define AS_QL 16384
#define AS_KV 32768           // + stage*16384 : Kh(8K) | Vh(8K)
#define AS_TOTAL (32768 + 2 * 16384)   // 65536

__global__ __launch_bounds__(256, 2) void attn_mma_kernel()
{
    extern __shared__ char smem[];
    uint32_t sb = smem_to_u32(smem);
    int tid = threadIdx.x;
    int wid = tid >> 5;
    int lane = tid & 31;

    int qt = 15 - blockIdx.y;     // longest first
    int bh = blockIdx.x;
    int q0 = qt * 128;
    size_t base = (size_t)bh * T_ * DH_;
    int nkt = 2 * qt + 2;

#pragma unroll
    for (int p = 0; p < 4; p++) {
        int idx = tid + p * 256;
        int row = idx >> 3;
        int ch  = idx & 7;
        uint32_t so = SMEM_SWIZZLE_128B(row * 128 + ch * 16);
        size_t g = base + (size_t)(q0 + row) * DH_ + ch * 8;
        cp16(sb + AS_QH + so, g_qh + g);
        cp16(sb + AS_QL + so, g_ql + g);
    }
    cp_commit();

    auto load_kv = [&](int j, int s) {
        uint32_t st = sb + AS_KV + s * 16384;
#pragma unroll
        for (int p = 0; p < 2; p++) {
            int idx = tid + p * 256;
            int row = idx >> 3;
            int ch  = idx & 7;
            uint32_t so = SMEM_SWIZZLE_128B(row * 128 + ch * 16);
            size_t g = base + (size_t)(j * 64 + row) * DH_ + ch * 8;
            cp16(st + so,        g_kh + g);
            cp16(st + 8192 + so, g_vh + g);
        }
        cp_commit();
    };

    load_kv(0, 0);

    uint32_t qh[4][4], ql[4][4];
    float O[8][4];
#pragma unroll
    for (int dt = 0; dt < 8; dt++)
#pragma unroll
        for (int c = 0; c < 4; c++) O[dt][c] = 0.f;
    float m0r = -1e30f, m1r = -1e30f, l0r = 0.f, l1r = 0.f;

    int g4 = lane >> 2;
    int c2 = 2 * (lane & 3);
    int a_row = lane & 15;
    int a_cb  = (lane >> 4) << 4;
    int bg     = lane >> 3;
    int bp_row = (lane & 7) + ((bg >> 1) << 3);
    int bp_cb  = (bg & 1) << 4;
    int v_row = (lane & 7) + ((lane >> 3) & 1) * 8;
    int v_ct  = (lane >> 4) & 1;

    for (int j = 0; j < nkt; j++) {
        int s = j & 1;
        if (j + 1 < nkt) {
            load_kv(j + 1, (j + 1) & 1);
            asm volatile("cp.async.wait_group 1;" ::: "memory");
        } else {
            asm volatile("cp.async.wait_group 0;" ::: "memory");
        }
        __syncthreads();

        if (j == 0) {
#pragma unroll
            for (int ks = 0; ks < 4; ks++) {
                uint32_t off = SMEM_SWIZZLE_128B((wid * 16 + a_row) * 128 + ks * 32 + a_cb);
                ldsm_x4(qh[ks], sb + AS_QH + off);
                ldsm_x4(ql[ks], sb + AS_QL + off);
            }
        }

        uint32_t stK = sb + AS_KV + s * 16384;
        uint32_t stV = stK + 8192;

        // ---- S = Q @ K^T (2-term, paired-K ldsm) ----
        float S[8][4];
#pragma unroll
        for (int jt = 0; jt < 8; jt++)
#pragma unroll
            for (int c = 0; c < 4; c++) S[jt][c] = 0.f;

#pragma unroll
        for (int jp = 0; jp < 4; jp++) {
#pragma unroll
            for (int ks = 0; ks < 4; ks++) {
                uint32_t off = SMEM_SWIZZLE_128B((jp * 16 + bp_row) * 128 + ks * 32 + bp_cb);
                uint32_t r4[4];
                ldsm_x4(r4, stK + off);
                mma_f16(S[2 * jp],     qh[ks], r4);
                mma_f16(S[2 * jp],     ql[ks], r4);
                mma_f16(S[2 * jp + 1], qh[ks], r4 + 2);
                mma_f16(S[2 * jp + 1], ql[ks], r4 + 2);
            }
        }

        if (j >= 2 * qt) {
            int r0 = q0 + wid * 16 + g4;
            int cb = j * 64 + c2;
#pragma unroll
            for (int jt = 0; jt < 8; jt++) {
                int c0 = cb + jt * 8;
                if (c0 > r0)     S[jt][0] = -1e30f;
                if (c0 + 1 > r0) S[jt][1] = -1e30f;
                if (c0 > r0 + 8)     S[jt][2] = -1e30f;
                if (c0 + 1 > r0 + 8) S[jt][3] = -1e30f;
            }
        }

        float mx0 = -1e30f, mx1 = -1e30f;
#pragma unroll
        for (int jt = 0; jt < 8; jt++) {
            mx0 = fmaxf(mx0, fmaxf(S[jt][0], S[jt][1]));
            mx1 = fmaxf(mx1, fmaxf(S[jt][2], S[jt][3]));
        }
        mx0 = fmaxf(mx0, __shfl_xor_sync(0xffffffffu, mx0, 1));
        mx0 = fmaxf(mx0, __shfl_xor_sync(0xffffffffu, mx0, 2));
        mx1 = fmaxf(mx1, __shfl_xor_sync(0xffffffffu, mx1, 1));
        mx1 = fmaxf(mx1, __shfl_xor_sync(0xffffffffu, mx1, 2));

        float mn0 = fmaxf(m0r, mx0), mn1 = fmaxf(m1r, mx1);
        float al0 = __expf(m0r - mn0), al1 = __expf(m1r - mn1);
        m0r = mn0; m1r = mn1;

        float s0 = 0.f, s1 = 0.f;
#pragma unroll
        for (int jt = 0; jt < 8; jt++) {
            S[jt][0] = __expf(S[jt][0] - mn0); s0 += S[jt][0];
            S[jt][1] = __expf(S[jt][1] - mn0); s0 += S[jt][1];
            S[jt][2] = __expf(S[jt][2] - mn1); s1 += S[jt][2];
            S[jt][3] = __expf(S[jt][3] - mn1); s1 += S[jt][3];
        }
        s0 += __shfl_xor_sync(0xffffffffu, s0, 1);
        s0 += __shfl_xor_sync(0xffffffffu, s0, 2);
        s1 += __shfl_xor_sync(0xffffffffu, s1, 1);
        s1 += __shfl_xor_sync(0xffffffffu, s1, 2);
        l0r = l0r * al0 + s0;
        l1r = l1r * al1 + s1;

#pragma unroll
        for (int dt = 0; dt < 8; dt++) {
            O[dt][0] *= al0; O[dt][1] *= al0;
            O[dt][2] *= al1; O[dt][3] *= al1;
        }

        // ---- pack P hi/lo IN PLACE (fp16) ----
#pragma unroll
        for (int ks2 = 0; ks2 < 4; ks2++) {
#pragma unroll
            for (int q = 0; q < 4; q++) {
                int tile = 2 * ks2 + (q >> 1);
                int cb = (q & 1) * 2;
                float p0 = S[tile][cb], p1 = S[tile][cb + 1];
                uint32_t hp = pack_h2(p0, p1);
                float2 bk = unpack_h2(hp);
                S[tile][cb]     = __uint_as_float(hp);
                S[tile][cb + 1] = __uint_as_float(pack_h2(p0 - bk.x, p1 - bk.y));
            }
        }

        // ---- O += P @ V (2-term, paired-trans ldsm) ----
#pragma unroll
        for (int dtp = 0; dtp < 4; dtp++) {
#pragma unroll
            for (int ks2 = 0; ks2 < 4; ks2++) {
                uint32_t ph[4] = {
                    __float_as_uint(S[2 * ks2][0]),     __float_as_uint(S[2 * ks2][2]),
                    __float_as_uint(S[2 * ks2 + 1][0]), __float_as_uint(S[2 * ks2 + 1][2])};
                uint32_t pl[4] = {
                    __float_as_uint(S[2 * ks2][1]),     __float_as_uint(S[2 * ks2][3]),
                    __float_as_uint(S[2 * ks2 + 1][1]), __float_as_uint(S[2 * ks2 + 1][3])};
                uint32_t off = SMEM_SWIZZLE_128B((ks2 * 16 + v_row) * 128 +
                                                 (2 * dtp + v_ct) * 16);
                uint32_t r4[4];
                ldsm_x4_trans(r4, stV + off);
                mma_f16(O[2 * dtp],     ph, r4);
                mma_f16(O[2 * dtp],     pl, r4);
                mma_f16(O[2 * dtp + 1], ph, r4 + 2);
                mma_f16(O[2 * dtp + 1], pl, r4 + 2);
            }
        }
        __syncthreads();
    }

    // ---- epilogue: y = O / l, single fp16 ----
    float li0 = 1.f / l0r, li1 = 1.f / l1r;
    int b = bh >> 4, h = bh & 15;
    int r0 = q0 + wid * 16 + g4;
#pragma unroll
    for (int dt = 0; dt < 8; dt++) {
        int d = dt * 8 + c2;
        {
            size_t off = (size_t)(b * T_ + r0) * C_ + h * DH_ + d;
            *(uint32_t*)(g_yh + off) = pack_h2(O[dt][0] * li0, O[dt][1] * li0);
        }
        {
            size_t off = (size_t)(b * T_ + r0 + 8) * C_ + h * DH_ + d;
            *(uint32_t*)(g_yh + off) = pack_h2(O[dt][2] * li1, O[dt][3] * li1);
        }
    }
}

// ---------------------------------------------------------------------------
extern "C" void kernel_launch(void* const* d_in, const int* in_sizes, int n_in,
                              void* d_out, int out_size)
{
    const float* x      = (const float*)d_in[0];
    const float* w_qkv  = (const float*)d_in[1];
    const float* w_proj = (const float*)d_in[2];
    float* out = (float*)d_out;
    (void)in_sizes; (void)n_in; (void)out_size;

    cudaFuncSetAttribute(mma_gemm_kernel,
                         cudaFuncAttributeMaxDynamicSharedMemorySize, SM_GEMM_TOTAL);
    cudaFuncSetAttribute(attn_mma_kernel,
                         cudaFuncAttributeMaxDynamicSharedMemorySize, AS_TOTAL);

    __half *xh, *yh, *wq, *wp;
    cudaGetSymbolAddress((void**)&xh, g_xh);
    cudaGetSymbolAddress((void**)&yh, g_yh);
    cudaGetSymbolAddress((void**)&wq, g_wqkvT);
    cudaGetSymbolAddress((void**)&wp, g_wprojT);

    // prep
    convert_x_kernel<<<M_ * K_ / (256 * 4), 256>>>(x);
    transpose_w_kernel<<<dim3(N_QKV / 32, K_ / 32), dim3(32, 8)>>>(w_qkv, wq, N_QKV);
    transpose_w_kernel<<<dim3(C_ / 32, K_ / 32), dim3(32, 8)>>>(w_proj, wp, C_);

    // QKV GEMM (1-term) with fused q-split/scale + k/v fp16 scatter
    mma_gemm_kernel<<<dim3(N_QKV / 64, M_ / 128), 256, SM_GEMM_TOTAL>>>(
        xh, wq, nullptr, 0);

    // tensor-core causal flash attention
    attn_mma_kernel<<<dim3(B_ * H_, T_ / 128), 256, AS_TOTAL>>>();

    // output projection GEMM (1-term)
    mma_gemm_kernel<<<dim3(C_ / 64, M_ / 128), 256, SM_GEMM_TOTAL>>>(
        yh, wp, out, 1);
}

// round 11
// speedup vs baseline: 2.5533x; 1.1399x over previous
#include <cuda_runtime.h>
#include <cuda_fp16.h>
#include <cstdint>
#include <cstring>

// Problem constants
#define B_   4
#define T_   2048
#define C_   1024
#define H_   16
#define DH_  64
#define M_   (B_ * T_)          // 8192
#define N_QKV (3 * C_)          // 3072
#define K_   1024

// ---------------------------------------------------------------------------
// Device-global scratch
// ---------------------------------------------------------------------------
__device__ __half g_qh[B_ * H_ * T_ * DH_];
__device__ __half g_ql[B_ * H_ * T_ * DH_];
__device__ __half g_kh[B_ * H_ * T_ * DH_];
__device__ __half g_vh[B_ * H_ * T_ * DH_];
__device__ __half g_xh[M_ * K_];
__device__ __half g_yh[M_ * C_];
__device__ __half g_wqkvT[N_QKV * K_];   // [N][K]
__device__ __half g_wprojT[C_ * K_];

#define SMEM_SWIZZLE_128B(o) ((o) ^ (((o) >> 3) & 0x70))

__device__ __forceinline__ uint32_t smem_to_u32(const void* p) {
    uint32_t a;
    asm("{ .reg .u64 t; cvta.to.shared.u64 t, %1; cvt.u32.u64 %0, t; }" : "=r"(a) : "l"(p));
    return a;
}
__device__ __forceinline__ void cp16(uint32_t saddr, const void* g) {
    asm volatile("cp.async.cg.shared.global [%0], [%1], 16;" :: "r"(saddr), "l"(g));
}
__device__ __forceinline__ void cp_commit() {
    asm volatile("cp.async.commit_group;" ::: "memory");
}
__device__ __forceinline__ void ldsm_x4(uint32_t* r, uint32_t addr) {
    asm volatile("ldmatrix.sync.aligned.m8n8.x4.shared.b16 {%0,%1,%2,%3}, [%4];"
        : "=r"(r[0]), "=r"(r[1]), "=r"(r[2]), "=r"(r[3]) : "r"(addr));
}
__device__ __forceinline__ void ldsm_x4_trans(uint32_t* r, uint32_t addr) {
    asm volatile("ldmatrix.sync.aligned.m8n8.x4.trans.shared.b16 {%0,%1,%2,%3}, [%4];"
        : "=r"(r[0]), "=r"(r[1]), "=r"(r[2]), "=r"(r[3]) : "r"(addr));
}
__device__ __forceinline__ void mma_f16(float* c, const uint32_t* a, const uint32_t* b) {
    asm volatile("mma.sync.aligned.m16n8k16.row.col.f32.f16.f16.f32 "
        "{%0,%1,%2,%3}, {%4,%5,%6,%7}, {%8,%9}, {%0,%1,%2,%3};"
        : "+f"(c[0]), "+f"(c[1]), "+f"(c[2]), "+f"(c[3])
        : "r"(a[0]), "r"(a[1]), "r"(a[2]), "r"(a[3]), "r"(b[0]), "r"(b[1]));
}
__device__ __forceinline__ uint32_t pack_h2(float lo, float hi) {
    __half2 h = __floats2half2_rn(lo, hi);
    uint32_t u; memcpy(&u, &h, 4); return u;
}
__device__ __forceinline__ float2 unpack_h2(uint32_t u) {
    __half2 h; memcpy(&h, &u, 4);
    return __half22float2(h);
}

// ---------------------------------------------------------------------------
// Prep: round x (fp32) to fp16
// ---------------------------------------------------------------------------
__global__ __launch_bounds__(256) void convert_x_kernel(const float* __restrict__ x)
{
    int idx = (blockIdx.x * 256 + threadIdx.x) * 4;
    float4 v = *(const float4*)(x + idx);
    float vv[4] = {v.x, v.y, v.z, v.w};
    __half h[4];
#pragma unroll
    for (int i = 0; i < 4; i++) h[i] = __float2half_rn(vv[i]);
    *(uint2*)(g_xh + idx) = *(uint2*)h;
}

// ---------------------------------------------------------------------------
// Prep: transpose W [K,N] -> WT [N,K] fp16
// ---------------------------------------------------------------------------
__global__ __launch_bounds__(256) void transpose_w_kernel(
    const float* __restrict__ W, __half* __restrict__ WT, int N)
{
    __shared__ float t[32][33];
    int n0 = blockIdx.x * 32, k0 = blockIdx.y * 32;
    int tx = threadIdx.x, ty = threadIdx.y;
#pragma unroll
    for (int i = 0; i < 4; i++)
        t[ty + i * 8][tx] = W[(size_t)(k0 + ty + i * 8) * N + n0 + tx];
    __syncthreads();
#pragma unroll
    for (int i = 0; i < 4; i++) {
        int n = n0 + ty + i * 8;
        int k = k0 + tx;
        WT[(size_t)n * K_ + k] = __float2half_rn(t[tx][ty + i * 8]);
    }
}

// ---------------------------------------------------------------------------
// Tensor-core GEMM, 1-term fp16: C = A @ B^T.
// CTA tile 128(M)x128(N), BK=64, 256 threads / 8 warps (2m x 4n),
// warp tile 64x32. Stage 32KB (A16|B16), double-buffered -> 2 CTAs/SM.
// mode 0: scatter q (fp16 hi/lo, scaled) / k,v (fp16); mode 1: f32 store.
// ---------------------------------------------------------------------------
#define STAGE_BYTES 32768
#define SM_GEMM_TOTAL (2 * STAGE_BYTES)   // 65536

__global__ __launch_bounds__(256, 2) void mma_gemm_kernel(
    const __half* __restrict__ Ah, const __half* __restrict__ Bm,
    float* __restrict__ out, int mode)
{
    extern __shared__ char smem[];
    uint32_t sbase = smem_to_u32(smem);

    int tid = threadIdx.x;
    int wid = tid >> 5;
    int lane = tid & 31;
    int wm = wid >> 2;          // 0..1 (m, 64 rows)
    int wn = wid & 3;           // 0..3 (n, 32 cols)

    int m0 = blockIdx.y * 128;
    int n0 = blockIdx.x * 128;

    float acc[4][4][4];
#pragma unroll
    for (int i = 0; i < 4; i++)
#pragma unroll
        for (int j = 0; j < 4; j++)
#pragma unroll
            for (int c = 0; c < 4; c++) acc[i][j][c] = 0.f;

    auto load_chunk = [&](int kt, int s) {
        uint32_t st = sbase + s * STAGE_BYTES;
#pragma unroll
        for (int p = 0; p < 4; p++) {
            int idx = tid + p * 256;       // 0..1023
            int row = idx >> 3;
            int ch  = idx & 7;
            uint32_t so = SMEM_SWIZZLE_128B(row * 128 + ch * 16);
            size_t ka = (size_t)(m0 + row) * K_ + kt * 64 + ch * 8;
            size_t kb = (size_t)(n0 + row) * K_ + kt * 64 + ch * 8;
            cp16(st + so,         Ah + ka);
            cp16(st + 16384 + so, Bm + kb);
        }
        cp_commit();
    };

    load_chunk(0, 0);

    int a_row = lane & 15;
    int a_cb  = (lane >> 4) << 4;
    int bg     = lane >> 3;
    int bp_row = (lane & 7) + ((bg >> 1) << 3);
    int bp_cb  = (bg & 1) << 4;

    for (int kt = 0; kt < 16; kt++) {
        int s = kt & 1;
        if (kt + 1 < 16) {
            load_chunk(kt + 1, (kt + 1) & 1);
            asm volatile("cp.async.wait_group 1;" ::: "memory");
        } else {
            asm volatile("cp.async.wait_group 0;" ::: "memory");
        }
        __syncthreads();

        uint32_t sA = sbase + s * STAGE_BYTES;
        uint32_t sB = sA + 16384;

#pragma unroll
        for (int ks = 0; ks < 4; ks++) {
            int kB = ks * 32;
            uint32_t ah[4][4], bh[4][2];
#pragma unroll
            for (int i = 0; i < 4; i++) {
                uint32_t off = SMEM_SWIZZLE_128B((wm * 64 + i * 16 + a_row) * 128 + kB + a_cb);
                ldsm_x4(ah[i], sA + off);
            }
#pragma unroll
            for (int jp = 0; jp < 2; jp++) {
                uint32_t off = SMEM_SWIZZLE_128B((wn * 32 + jp * 16 + bp_row) * 128 + kB + bp_cb);
                uint32_t r4[4];
                ldsm_x4(r4, sB + off);
                bh[2 * jp][0] = r4[0]; bh[2 * jp][1] = r4[1];
                bh[2 * jp + 1][0] = r4[2]; bh[2 * jp + 1][1] = r4[3];
            }
#pragma unroll
            for (int i = 0; i < 4; i++)
#pragma unroll
                for (int j = 0; j < 4; j++) mma_f16(acc[i][j], ah[i], bh[j]);
        }
        __syncthreads();
    }

    int r4i = lane >> 2;
    int cp2 = (lane & 3) * 2;

    if (mode == 1) {
#pragma unroll
        for (int i = 0; i < 4; i++)
#pragma unroll
            for (int j = 0; j < 4; j++) {
                int n = n0 + wn * 32 + j * 8 + cp2;
#pragma unroll
                for (int rr = 0; rr < 2; rr++) {
                    int m = m0 + wm * 64 + i * 16 + r4i + rr * 8;
                    *(float2*)(out + (size_t)m * C_ + n) =
                        make_float2(acc[i][j][rr * 2], acc[i][j][rr * 2 + 1]);
                }
            }
    } else {
        int which = n0 >> 10;      // constant per CTA (128 | 1024)
#pragma unroll
        for (int i = 0; i < 4; i++)
#pragma unroll
            for (int j = 0; j < 4; j++) {
                int n = n0 + wn * 32 + j * 8 + cp2;
                int h = (n & 1023) >> 6;
                int d = n & 63;
#pragma unroll
                for (int rr = 0; rr < 2; rr++) {
                    int m = m0 + wm * 64 + i * 16 + r4i + rr * 8;
                    int b = m >> 11;
                    int t = m & 2047;
                    size_t off = (size_t)(((b << 4) + h) * T_ + t) * DH_ + d;
                    float v0 = acc[i][j][rr * 2];
                    float v1 = acc[i][j][rr * 2 + 1];
                    if (which == 0) {           // Q: scale + hi/lo split
                        v0 *= 0.125f; v1 *= 0.125f;
                        uint32_t hp = pack_h2(v0, v1);
                        float2 bk = unpack_h2(hp);
                        *(uint32_t*)(g_qh + off) = hp;
                        *(uint32_t*)(g_ql + off) = pack_h2(v0 - bk.x, v1 - bk.y);
                    } else if (which == 1) {    // K
                        *(uint32_t*)(g_kh + off) = pack_h2(v0, v1);
                    } else {                    // V
                        *(uint32_t*)(g_vh + off) = pack_h2(v0, v1);
                    }
                }
            }
    }
}

// ---------------------------------------------------------------------------
// Tensor-core causal flash attention.
// Q split hi/lo (2-term S), P single fp16 (1-term PV), K/V single fp16.
// 2 CTAs/SM, LPT grid.
// ---------------------------------------------------------------------------
#define AS_QH 0
#define AS_QL 16384
#define AS_KV 32768           // + stage*16384 : Kh(8K) | Vh(8K)
#define AS_TOTAL (32768 + 2 * 16384)   // 65536

__global__ __launch_bounds__(256, 2) void attn_mma_kernel()
{
    extern __shared__ char smem[];
    uint32_t sb = smem_to_u32(smem);
    int tid = threadIdx.x;
    int wid = tid >> 5;
    int lane = tid & 31;

    int qt = 15 - blockIdx.y;     // longest first
    int bh = blockIdx.x;
    int q0 = qt * 128;
    size_t base = (size_t)bh * T_ * DH_;
    int nkt = 2 * qt + 2;

#pragma unroll
    for (int p = 0; p < 4; p++) {
        int idx = tid + p * 256;
        int row = idx >> 3;
        int ch  = idx & 7;
        uint32_t so = SMEM_SWIZZLE_128B(row * 128 + ch * 16);
        size_t g = base + (size_t)(q0 + row) * DH_ + ch * 8;
        cp16(sb + AS_QH + so, g_qh + g);
        cp16(sb + AS_QL + so, g_ql + g);
    }
    cp_commit();

    auto load_kv = [&](int j, int s) {
        uint32_t st = sb + AS_KV + s * 16384;
#pragma unroll
        for (int p = 0; p < 2; p++) {
            int idx = tid + p * 256;
            int row = idx >> 3;
            int ch  = idx & 7;
            uint32_t so = SMEM_SWIZZLE_128B(row * 128 + ch * 16);
            size_t g = base + (size_t)(j * 64 + row) * DH_ + ch * 8;
            cp16(st + so,        g_kh + g);
            cp16(st + 8192 + so, g_vh + g);
        }
        cp_commit();
    };

    load_kv(0, 0);

    uint32_t qh[4][4], ql[4][4];
    float O[8][4];
#pragma unroll
    for (int dt = 0; dt < 8; dt++)
#pragma unroll
        for (int c = 0; c < 4; c++) O[dt][c] = 0.f;
    float m0r = -1e30f, m1r = -1e30f, l0r = 0.f, l1r = 0.f;

    int g4 = lane >> 2;
    int c2 = 2 * (lane & 3);
    int a_row = lane & 15;
    int a_cb  = (lane >> 4) << 4;
    int bg     = lane >> 3;
    int bp_row = (lane & 7) + ((bg >> 1) << 3);
    int bp_cb  = (bg & 1) << 4;
    int v_row = (lane & 7) + ((lane >> 3) & 1) * 8;
    int v_ct  = (lane >> 4) & 1;

    for (int j = 0; j < nkt; j++) {
        int s = j & 1;
        if (j + 1 < nkt) {
            load_kv(j + 1, (j + 1) & 1);
            asm volatile("cp.async.wait_group 1;" ::: "memory");
        } else {
            asm volatile("cp.async.wait_group 0;" ::: "memory");
        }
        __syncthreads();

        if (j == 0) {
#pragma unroll
            for (int ks = 0; ks < 4; ks++) {
                uint32_t off = SMEM_SWIZZLE_128B((wid * 16 + a_row) * 128 + ks * 32 + a_cb);
                ldsm_x4(qh[ks], sb + AS_QH + off);
                ldsm_x4(ql[ks], sb + AS_QL + off);
            }
        }

        uint32_t stK = sb + AS_KV + s * 16384;
        uint32_t stV = stK + 8192;

        // ---- S = Q @ K^T (2-term, paired-K ldsm) ----
        float S[8][4];
#pragma unroll
        for (int jt = 0; jt < 8; jt++)
#pragma unroll
            for (int c = 0; c < 4; c++) S[jt][c] = 0.f;

#pragma unroll
        for (int jp = 0; jp < 4; jp++) {
#pragma unroll
            for (int ks = 0; ks < 4; ks++) {
                uint32_t off = SMEM_SWIZZLE_128B((jp * 16 + bp_row) * 128 + ks * 32 + bp_cb);
                uint32_t r4[4];
                ldsm_x4(r4, stK + off);
                mma_f16(S[2 * jp],     qh[ks], r4);
                mma_f16(S[2 * jp],     ql[ks], r4);
                mma_f16(S[2 * jp + 1], qh[ks], r4 + 2);
                mma_f16(S[2 * jp + 1], ql[ks], r4 + 2);
            }
        }

        if (j >= 2 * qt) {
            int r0 = q0 + wid * 16 + g4;
            int cb = j * 64 + c2;
#pragma unroll
            for (int jt = 0; jt < 8; jt++) {
                int c0 = cb + jt * 8;
                if (c0 > r0)     S[jt][0] = -1e30f;
                if (c0 + 1 > r0) S[jt][1] = -1e30f;
                if (c0 > r0 + 8)     S[jt][2] = -1e30f;
                if (c0 + 1 > r0 + 8) S[jt][3] = -1e30f;
            }
        }

        float mx0 = -1e30f, mx1 = -1e30f;
#pragma unroll
        for (int jt = 0; jt < 8; jt++) {
            mx0 = fmaxf(mx0, fmaxf(S[jt][0], S[jt][1]));
            mx1 = fmaxf(mx1, fmaxf(S[jt][2], S[jt][3]));
        }
        mx0 = fmaxf(mx0, __shfl_xor_sync(0xffffffffu, mx0, 1));
        mx0 = fmaxf(mx0, __shfl_xor_sync(0xffffffffu, mx0, 2));
        mx1 = fmaxf(mx1, __shfl_xor_sync(0xffffffffu, mx1, 1));
        mx1 = fmaxf(mx1, __shfl_xor_sync(0xffffffffu, mx1, 2));

        float mn0 = fmaxf(m0r, mx0), mn1 = fmaxf(m1r, mx1);
        float al0 = __expf(m0r - mn0), al1 = __expf(m1r - mn1);
        m0r = mn0; m1r = mn1;

        float s0 = 0.f, s1 = 0.f;
#pragma unroll
        for (int jt = 0; jt < 8; jt++) {
            S[jt][0] = __expf(S[jt][0] - mn0); s0 += S[jt][0];
            S[jt][1] = __expf(S[jt][1] - mn0); s0 += S[jt][1];
            S[jt][2] = __expf(S[jt][2] - mn1); s1 += S[jt][2];
            S[jt][3] = __expf(S[jt][3] - mn1); s1 += S[jt][3];
        }
        s0 += __shfl_xor_sync(0xffffffffu, s0, 1);
        s0 += __shfl_xor_sync(0xffffffffu, s0, 2);
        s1 += __shfl_xor_sync(0xffffffffu, s1, 1);
        s1 += __shfl_xor_sync(0xffffffffu, s1, 2);
        l0r = l0r * al0 + s0;
        l1r = l1r * al1 + s1;

#pragma unroll
        for (int dt = 0; dt < 8; dt++) {
            O[dt][0] *= al0; O[dt][1] *= al0;
            O[dt][2] *= al1; O[dt][3] *= al1;
        }

        // ---- pack P (single fp16) IN PLACE: S[tile][cb] = packed pair ----
#pragma unroll
        for (int ks2 = 0; ks2 < 4; ks2++) {
#pragma unroll
            for (int q = 0; q < 4; q++) {
                int tile = 2 * ks2 + (q >> 1);
                int cb = (q & 1) * 2;
                S[tile][cb] = __uint_as_float(pack_h2(S[tile][cb], S[tile][cb + 1]));
            }
        }

        // ---- O += P @ V (1-term, paired-trans ldsm) ----
#pragma unroll
        for (int dtp = 0; dtp < 4; dtp++) {
#pragma unroll
            for (int ks2 = 0; ks2 < 4; ks2++) {
                uint32_t ph[4] = {
                    __float_as_uint(S[2 * ks2][0]),     __float_as_uint(S[2 * ks2][2]),
                    __float_as_uint(S[2 * ks2 + 1][0]), __float_as_uint(S[2 * ks2 + 1][2])};
                uint32_t off = SMEM_SWIZZLE_128B((ks2 * 16 + v_row) * 128 +
                                                 (2 * dtp + v_ct) * 16);
                uint32_t r4[4];
                ldsm_x4_trans(r4, stV + off);
                mma_f16(O[2 * dtp],     ph, r4);
                mma_f16(O[2 * dtp + 1], ph, r4 + 2);
            }
        }
        __syncthreads();
    }

    // ---- epilogue: y = O / l, single fp16 ----
    float li0 = 1.f / l0r, li1 = 1.f / l1r;
    int b = bh >> 4, h = bh & 15;
    int r0 = q0 + wid * 16 + g4;
#pragma unroll
    for (int dt = 0; dt < 8; dt++) {
        int d = dt * 8 + c2;
        {
            size_t off = (size_t)(b * T_ + r0) * C_ + h * DH_ + d;
            *(uint32_t*)(g_yh + off) = pack_h2(O[dt][0] * li0, O[dt][1] * li0);
        }
        {
            size_t off = (size_t)(b * T_ + r0 + 8) * C_ + h * DH_ + d;
            *(uint32_t*)(g_yh + off) = pack_h2(O[dt][2] * li1, O[dt][3] * li1);
        }
    }
}

// ---------------------------------------------------------------------------
extern "C" void kernel_launch(void* const* d_in, const int* in_sizes, int n_in,
                              void* d_out, int out_size)
{
    const float* x      = (const float*)d_in[0];
    const float* w_qkv  = (const float*)d_in[1];
    const float* w_proj = (const float*)d_in[2];
    float* out = (float*)d_out;
    (void)in_sizes; (void)n_in; (void)out_size;

    cudaFuncSetAttribute(mma_gemm_kernel,
                         cudaFuncAttributeMaxDynamicSharedMemorySize, SM_GEMM_TOTAL);
    cudaFuncSetAttribute(attn_mma_kernel,
                         cudaFuncAttributeMaxDynamicSharedMemorySize, AS_TOTAL);

    __half *xh, *yh, *wq, *wp;
    cudaGetSymbolAddress((void**)&xh, g_xh);
    cudaGetSymbolAddress((void**)&yh, g_yh);
    cudaGetSymbolAddress((void**)&wq, g_wqkvT);
    cudaGetSymbolAddress((void**)&wp, g_wprojT);

    // prep
    convert_x_kernel<<<M_ * K_ / (256 * 4), 256>>>(x);
    transpose_w_kernel<<<dim3(N_QKV / 32, K_ / 32), dim3(32, 8)>>>(w_qkv, wq, N_QKV);
    transpose_w_kernel<<<dim3(C_ / 32, K_ / 32), dim3(32, 8)>>>(w_proj, wp, C_);

    // QKV GEMM (1-term, 128x128 tile) with fused q-split/scale + k/v scatter
    mma_gemm_kernel<<<dim3(N_QKV / 128, M_ / 128), 256, SM_GEMM_TOTAL>>>(
        xh, wq, nullptr, 0);

    // tensor-core causal flash attention
    attn_mma_kernel<<<dim3(B_ * H_, T_ / 128), 256, AS_TOTAL>>>();

    // output projection GEMM (1-term, 128x128 tile)
    mma_gemm_kernel<<<dim3(C_ / 128, M_ / 128), 256, SM_GEMM_TOTAL>>>(
        yh, wp, out, 1);
}

// round 12
// speedup vs baseline: 2.7794x; 1.0886x over previous
#include <cuda_runtime.h>
#include <cuda_fp16.h>
#include <cstdint>
#include <cstring>

// Problem constants
#define B_   4
#define T_   2048
#define C_   1024
#define H_   16
#define DH_  64
#define M_   (B_ * T_)          // 8192
#define N_QKV (3 * C_)          // 3072
#define K_   1024

// ---------------------------------------------------------------------------
// Device-global scratch
// ---------------------------------------------------------------------------
__device__ __half g_qh[B_ * H_ * T_ * DH_];
__device__ __half g_kh[B_ * H_ * T_ * DH_];
__device__ __half g_vh[B_ * H_ * T_ * DH_];
__device__ __half g_xh[M_ * K_];
__device__ __half g_yh[M_ * C_];
__device__ __half g_wqkvT[N_QKV * K_];   // [N][K]
__device__ __half g_wprojT[C_ * K_];

#define SMEM_SWIZZLE_128B(o) ((o) ^ (((o) >> 3) & 0x70))

__device__ __forceinline__ uint32_t smem_to_u32(const void* p) {
    uint32_t a;
    asm("{ .reg .u64 t; cvta.to.shared.u64 t, %1; cvt.u32.u64 %0, t; }" : "=r"(a) : "l"(p));
    return a;
}
__device__ __forceinline__ void cp16(uint32_t saddr, const void* g) {
    asm volatile("cp.async.cg.shared.global [%0], [%1], 16;" :: "r"(saddr), "l"(g));
}
__device__ __forceinline__ void cp_commit() {
    asm volatile("cp.async.commit_group;" ::: "memory");
}
__device__ __forceinline__ void ldsm_x4(uint32_t* r, uint32_t addr) {
    asm volatile("ldmatrix.sync.aligned.m8n8.x4.shared.b16 {%0,%1,%2,%3}, [%4];"
        : "=r"(r[0]), "=r"(r[1]), "=r"(r[2]), "=r"(r[3]) : "r"(addr));
}
__device__ __forceinline__ void ldsm_x4_trans(uint32_t* r, uint32_t addr) {
    asm volatile("ldmatrix.sync.aligned.m8n8.x4.trans.shared.b16 {%0,%1,%2,%3}, [%4];"
        : "=r"(r[0]), "=r"(r[1]), "=r"(r[2]), "=r"(r[3]) : "r"(addr));
}
__device__ __forceinline__ void mma_f16(float* c, const uint32_t* a, const uint32_t* b) {
    asm volatile("mma.sync.aligned.m16n8k16.row.col.f32.f16.f16.f32 "
        "{%0,%1,%2,%3}, {%4,%5,%6,%7}, {%8,%9}, {%0,%1,%2,%3};"
        : "+f"(c[0]), "+f"(c[1]), "+f"(c[2]), "+f"(c[3])
        : "r"(a[0]), "r"(a[1]), "r"(a[2]), "r"(a[3]), "r"(b[0]), "r"(b[1]));
}
__device__ __forceinline__ uint32_t pack_h2(float lo, float hi) {
    __half2 h = __floats2half2_rn(lo, hi);
    uint32_t u; memcpy(&u, &h, 4); return u;
}

// ---------------------------------------------------------------------------
// Fused prep kernel: blockIdx partition.
//  [0, 8192)           : round x -> fp16      (256 thr, 4 elems each)
//  [8192, 11264)       : transpose w_qkv (96x32 tiles of 32x32)
//  [11264, 12288)      : transpose w_proj (32x32 tiles)
// ---------------------------------------------------------------------------
#define PREP_X_BLOCKS  (M_ * K_ / (256 * 4))          // 8192
#define PREP_WQ_BLOCKS ((N_QKV / 32) * (K_ / 32))     // 3072
#define PREP_WP_BLOCKS ((C_ / 32) * (K_ / 32))        // 1024
#define PREP_BLOCKS (PREP_X_BLOCKS + PREP_WQ_BLOCKS + PREP_WP_BLOCKS)

__global__ __launch_bounds__(256) void prep_kernel(
    const float* __restrict__ x,
    const float* __restrict__ wqkv,
    const float* __restrict__ wproj)
{
    __shared__ float t[32][33];
    int bid = blockIdx.x;
    int tid = threadIdx.x;

    if (bid < PREP_X_BLOCKS) {
        int idx = (bid * 256 + tid) * 4;
        float4 v = *(const float4*)(x + idx);
        float vv[4] = {v.x, v.y, v.z, v.w};
        __half h[4];
#pragma unroll
        for (int i = 0; i < 4; i++) h[i] = __float2half_rn(vv[i]);
        *(uint2*)(g_xh + idx) = *(uint2*)h;
        return;
    }

    const float* W;
    __half* WT;
    int N, bx, by;
    if (bid < PREP_X_BLOCKS + PREP_WQ_BLOCKS) {
        int b = bid - PREP_X_BLOCKS;
        W = wqkv; WT = g_wqkvT; N = N_QKV;
        bx = b % (N_QKV / 32); by = b / (N_QKV / 32);
    } else {
        int b = bid - PREP_X_BLOCKS - PREP_WQ_BLOCKS;
        W = wproj; WT = g_wprojT; N = C_;
        bx = b % (C_ / 32); by = b / (C_ / 32);
    }
    int n0 = bx * 32, k0 = by * 32;
    int tx = tid & 31, ty = tid >> 5;    // 32 x 8
#pragma unroll
    for (int i = 0; i < 4; i++)
        t[ty + i * 8][tx] = W[(size_t)(k0 + ty + i * 8) * N + n0 + tx];
    __syncthreads();
#pragma unroll
    for (int i = 0; i < 4; i++) {
        int n = n0 + ty + i * 8;
        int k = k0 + tx;
        WT[(size_t)n * K_ + k] = __float2half_rn(t[tx][ty + i * 8]);
    }
}

// ---------------------------------------------------------------------------
// Tensor-core GEMM, 1-term fp16: C = A @ B^T.
// CTA tile 128x128, BK=64, 8 warps (2m x 4n), warp tile 64x32.
// Stage 32KB (A16|B16), double-buffered -> 2 CTAs/SM.
// mode 0: scatter q (scaled fp16) / k / v; mode 1: f32 store.
// ---------------------------------------------------------------------------
#define STAGE_BYTES 32768
#define SM_GEMM_TOTAL (2 * STAGE_BYTES)   // 65536

__global__ __launch_bounds__(256, 2) void mma_gemm_kernel(
    const __half* __restrict__ Ah, const __half* __restrict__ Bm,
    float* __restrict__ out, int mode)
{
    extern __shared__ char smem[];
    uint32_t sbase = smem_to_u32(smem);

    int tid = threadIdx.x;
    int wid = tid >> 5;
    int lane = tid & 31;
    int wm = wid >> 2;          // 0..1
    int wn = wid & 3;           // 0..3

    int m0 = blockIdx.y * 128;
    int n0 = blockIdx.x * 128;

    float acc[4][4][4];
#pragma unroll
    for (int i = 0; i < 4; i++)
#pragma unroll
        for (int j = 0; j < 4; j++)
#pragma unroll
            for (int c = 0; c < 4; c++) acc[i][j][c] = 0.f;

    auto load_chunk = [&](int kt, int s) {
        uint32_t st = sbase + s * STAGE_BYTES;
#pragma unroll
        for (int p = 0; p < 4; p++) {
            int idx = tid + p * 256;
            int row = idx >> 3;
            int ch  = idx & 7;
            uint32_t so = SMEM_SWIZZLE_128B(row * 128 + ch * 16);
            size_t ka = (size_t)(m0 + row) * K_ + kt * 64 + ch * 8;
            size_t kb = (size_t)(n0 + row) * K_ + kt * 64 + ch * 8;
            cp16(st + so,         Ah + ka);
            cp16(st + 16384 + so, Bm + kb);
        }
        cp_commit();
    };

    load_chunk(0, 0);

    int a_row = lane & 15;
    int a_cb  = (lane >> 4) << 4;
    int bg     = lane >> 3;
    int bp_row = (lane & 7) + ((bg >> 1) << 3);
    int bp_cb  = (bg & 1) << 4;

    for (int kt = 0; kt < 16; kt++) {
        int s = kt & 1;
        if (kt + 1 < 16) {
            load_chunk(kt + 1, (kt + 1) & 1);
            asm volatile("cp.async.wait_group 1;" ::: "memory");
        } else {
            asm volatile("cp.async.wait_group 0;" ::: "memory");
        }
        __syncthreads();

        uint32_t sA = sbase + s * STAGE_BYTES;
        uint32_t sB = sA + 16384;

#pragma unroll
        for (int ks = 0; ks < 4; ks++) {
            int kB = ks * 32;
            uint32_t ah[4][4], bh[4][2];
#pragma unroll
            for (int i = 0; i < 4; i++) {
                uint32_t off = SMEM_SWIZZLE_128B((wm * 64 + i * 16 + a_row) * 128 + kB + a_cb);
                ldsm_x4(ah[i], sA + off);
            }
#pragma unroll
            for (int jp = 0; jp < 2; jp++) {
                uint32_t off = SMEM_SWIZZLE_128B((wn * 32 + jp * 16 + bp_row) * 128 + kB + bp_cb);
                uint32_t r4[4];
                ldsm_x4(r4, sB + off);
                bh[2 * jp][0] = r4[0]; bh[2 * jp][1] = r4[1];
                bh[2 * jp + 1][0] = r4[2]; bh[2 * jp + 1][1] = r4[3];
            }
#pragma unroll
            for (int i = 0; i < 4; i++)
#pragma unroll
                for (int j = 0; j < 4; j++) mma_f16(acc[i][j], ah[i], bh[j]);
        }
        __syncthreads();
    }

    int r4i = lane >> 2;
    int cp2 = (lane & 3) * 2;

    if (mode == 1) {
#pragma unroll
        for (int i = 0; i < 4; i++)
#pragma unroll
            for (int j = 0; j < 4; j++) {
                int n = n0 + wn * 32 + j * 8 + cp2;
#pragma unroll
                for (int rr = 0; rr < 2; rr++) {
                    int m = m0 + wm * 64 + i * 16 + r4i + rr * 8;
                    *(float2*)(out + (size_t)m * C_ + n) =
                        make_float2(acc[i][j][rr * 2], acc[i][j][rr * 2 + 1]);
                }
            }
    } else {
        int which = n0 >> 10;      // constant per CTA
        __half* dst = (which == 0) ? g_qh : (which == 1) ? g_kh : g_vh;
        float scale = (which == 0) ? 0.125f : 1.0f;
#pragma unroll
        for (int i = 0; i < 4; i++)
#pragma unroll
            for (int j = 0; j < 4; j++) {
                int n = n0 + wn * 32 + j * 8 + cp2;
                int h = (n & 1023) >> 6;
                int d = n & 63;
#pragma unroll
                for (int rr = 0; rr < 2; rr++) {
                    int m = m0 + wm * 64 + i * 16 + r4i + rr * 8;
                    int b = m >> 11;
                    int t = m & 2047;
                    size_t off = (size_t)(((b << 4) + h) * T_ + t) * DH_ + d;
                    *(uint32_t*)(dst + off) =
                        pack_h2(acc[i][j][rr * 2] * scale, acc[i][j][rr * 2 + 1] * scale);
                }
            }
    }
}

// ---------------------------------------------------------------------------
// Tensor-core causal flash attention — all 1-term fp16 (Q, K, V, P single).
// Stage: Q(16K) + 2 x (K 8K | V 8K) = 48K -> 2 CTAs/SM. LPT grid.
// ---------------------------------------------------------------------------
#define AS_Q  0
#define AS_KV 16384           // + stage*16384 : Kh(8K) | Vh(8K)
#define AS_TOTAL (16384 + 2 * 16384)   // 49152

__global__ __launch_bounds__(256, 2) void attn_mma_kernel()
{
    extern __shared__ char smem[];
    uint32_t sb = smem_to_u32(smem);
    int tid = threadIdx.x;
    int wid = tid >> 5;
    int lane = tid & 31;

    int qt = 15 - blockIdx.y;     // longest first
    int bh = blockIdx.x;
    int q0 = qt * 128;
    size_t base = (size_t)bh * T_ * DH_;
    int nkt = 2 * qt + 2;

#pragma unroll
    for (int p = 0; p < 4; p++) {
        int idx = tid + p * 256;
        int row = idx >> 3;
        int ch  = idx & 7;
        uint32_t so = SMEM_SWIZZLE_128B(row * 128 + ch * 16);
        cp16(sb + AS_Q + so, g_qh + base + (size_t)(q0 + row) * DH_ + ch * 8);
    }
    cp_commit();

    auto load_kv = [&](int j, int s) {
        uint32_t st = sb + AS_KV + s * 16384;
#pragma unroll
        for (int p = 0; p < 2; p++) {
            int idx = tid + p * 256;
            int row = idx >> 3;
            int ch  = idx & 7;
            uint32_t so = SMEM_SWIZZLE_128B(row * 128 + ch * 16);
            size_t g = base + (size_t)(j * 64 + row) * DH_ + ch * 8;
            cp16(st + so,        g_kh + g);
            cp16(st + 8192 + so, g_vh + g);
        }
        cp_commit();
    };

    load_kv(0, 0);

    uint32_t qh[4][4];
    float O[8][4];
#pragma unroll
    for (int dt = 0; dt < 8; dt++)
#pragma unroll
        for (int c = 0; c < 4; c++) O[dt][c] = 0.f;
    float m0r = -1e30f, m1r = -1e30f, l0r = 0.f, l1r = 0.f;

    int g4 = lane >> 2;
    int c2 = 2 * (lane & 3);
    int a_row = lane & 15;
    int a_cb  = (lane >> 4) << 4;
    int bg     = lane >> 3;
    int bp_row = (lane & 7) + ((bg >> 1) << 3);
    int bp_cb  = (bg & 1) << 4;
    int v_row = (lane & 7) + ((lane >> 3) & 1) * 8;
    int v_ct  = (lane >> 4) & 1;

    for (int j = 0; j < nkt; j++) {
        int s = j & 1;
        if (j + 1 < nkt) {
            load_kv(j + 1, (j + 1) & 1);
            asm volatile("cp.async.wait_group 1;" ::: "memory");
        } else {
            asm volatile("cp.async.wait_group 0;" ::: "memory");
        }
        __syncthreads();

        if (j == 0) {
#pragma unroll
            for (int ks = 0; ks < 4; ks++) {
                uint32_t off = SMEM_SWIZZLE_128B((wid * 16 + a_row) * 128 + ks * 32 + a_cb);
                ldsm_x4(qh[ks], sb + AS_Q + off);
            }
        }

        uint32_t stK = sb + AS_KV + s * 16384;
        uint32_t stV = stK + 8192;

        // ---- S = Q @ K^T (1-term, paired-K ldsm) ----
        float S[8][4];
#pragma unroll
        for (int jt = 0; jt < 8; jt++)
#pragma unroll
            for (int c = 0; c < 4; c++) S[jt][c] = 0.f;

#pragma unroll
        for (int jp = 0; jp < 4; jp++) {
#pragma unroll
            for (int ks = 0; ks < 4; ks++) {
                uint32_t off = SMEM_SWIZZLE_128B((jp * 16 + bp_row) * 128 + ks * 32 + bp_cb);
                uint32_t r4[4];
                ldsm_x4(r4, stK + off);
                mma_f16(S[2 * jp],     qh[ks], r4);
                mma_f16(S[2 * jp + 1], qh[ks], r4 + 2);
            }
        }

        if (j >= 2 * qt) {
            int r0 = q0 + wid * 16 + g4;
            int cb = j * 64 + c2;
#pragma unroll
            for (int jt = 0; jt < 8; jt++) {
                int c0 = cb + jt * 8;
                if (c0 > r0)     S[jt][0] = -1e30f;
                if (c0 + 1 > r0) S[jt][1] = -1e30f;
                if (c0 > r0 + 8)     S[jt][2] = -1e30f;
                if (c0 + 1 > r0 + 8) S[jt][3] = -1e30f;
            }
        }

        float mx0 = -1e30f, mx1 = -1e30f;
#pragma unroll
        for (int jt = 0; jt < 8; jt++) {
            mx0 = fmaxf(mx0, fmaxf(S[jt][0], S[jt][1]));
            mx1 = fmaxf(mx1, fmaxf(S[jt][2], S[jt][3]));
        }
        mx0 = fmaxf(mx0, __shfl_xor_sync(0xffffffffu, mx0, 1));
        mx0 = fmaxf(mx0, __shfl_xor_sync(0xffffffffu, mx0, 2));
        mx1 = fmaxf(mx1, __shfl_xor_sync(0xffffffffu, mx1, 1));
        mx1 = fmaxf(mx1, __shfl_xor_sync(0xffffffffu, mx1, 2));

        float mn0 = fmaxf(m0r, mx0), mn1 = fmaxf(m1r, mx1);
        float al0 = __expf(m0r - mn0), al1 = __expf(m1r - mn1);
        m0r = mn0; m1r = mn1;

        float s0 = 0.f, s1 = 0.f;
#pragma unroll
        for (int jt = 0; jt < 8; jt++) {
            S[jt][0] = __expf(S[jt][0] - mn0); s0 += S[jt][0];
            S[jt][1] = __expf(S[jt][1] - mn0); s0 += S[jt][1];
            S[jt][2] = __expf(S[jt][2] - mn1); s1 += S[jt][2];
            S[jt][3] = __expf(S[jt][3] - mn1); s1 += S[jt][3];
        }
        s0 += __shfl_xor_sync(0xffffffffu, s0, 1);
        s0 += __shfl_xor_sync(0xffffffffu, s0, 2);
        s1 += __shfl_xor_sync(0xffffffffu, s1, 1);
        s1 += __shfl_xor_sync(0xffffffffu, s1, 2);
        l0r = l0r * al0 + s0;
        l1r = l1r * al1 + s1;

#pragma unroll
        for (int dt = 0; dt < 8; dt++) {
            O[dt][0] *= al0; O[dt][1] *= al0;
            O[dt][2] *= al1; O[dt][3] *= al1;
        }

        // ---- pack P (single fp16) IN PLACE ----
#pragma unroll
        for (int ks2 = 0; ks2 < 4; ks2++) {
#pragma unroll
            for (int q = 0; q < 4; q++) {
                int tile = 2 * ks2 + (q >> 1);
                int cb = (q & 1) * 2;
                S[tile][cb] = __uint_as_float(pack_h2(S[tile][cb], S[tile][cb + 1]));
            }
        }

        // ---- O += P @ V (1-term, paired-trans ldsm) ----
#pragma unroll
        for (int dtp = 0; dtp < 4; dtp++) {
#pragma unroll
            for (int ks2 = 0; ks2 < 4; ks2++) {
                uint32_t ph[4] = {
                    __float_as_uint(S[2 * ks2][0]),     __float_as_uint(S[2 * ks2][2]),
                    __float_as_uint(S[2 * ks2 + 1][0]), __float_as_uint(S[2 * ks2 + 1][2])};
                uint32_t off = SMEM_SWIZZLE_128B((ks2 * 16 + v_row) * 128 +
                                                 (2 * dtp + v_ct) * 16);
                uint32_t r4[4];
                ldsm_x4_trans(r4, stV + off);
                mma_f16(O[2 * dtp],     ph, r4);
                mma_f16(O[2 * dtp + 1], ph, r4 + 2);
            }
        }
        __syncthreads();
    }

    // ---- epilogue: y = O / l, single fp16 ----
    float li0 = 1.f / l0r, li1 = 1.f / l1r;
    int b = bh >> 4, h = bh & 15;
    int r0 = q0 + wid * 16 + g4;
#pragma unroll
    for (int dt = 0; dt < 8; dt++) {
        int d = dt * 8 + c2;
        {
            size_t off = (size_t)(b * T_ + r0) * C_ + h * DH_ + d;
            *(uint32_t*)(g_yh + off) = pack_h2(O[dt][0] * li0, O[dt][1] * li0);
        }
        {
            size_t off = (size_t)(b * T_ + r0 + 8) * C_ + h * DH_ + d;
            *(uint32_t*)(g_yh + off) = pack_h2(O[dt][2] * li1, O[dt][3] * li1);
        }
    }
}

// ---------------------------------------------------------------------------
extern "C" void kernel_launch(void* const* d_in, const int* in_sizes, int n_in,
                              void* d_out, int out_size)
{
    const float* x      = (const float*)d_in[0];
    const float* w_qkv  = (const float*)d_in[1];
    const float* w_proj = (const float*)d_in[2];
    float* out = (float*)d_out;
    (void)in_sizes; (void)n_in; (void)out_size;

    cudaFuncSetAttribute(mma_gemm_kernel,
                         cudaFuncAttributeMaxDynamicSharedMemorySize, SM_GEMM_TOTAL);
    cudaFuncSetAttribute(attn_mma_kernel,
                         cudaFuncAttributeMaxDynamicSharedMemorySize, AS_TOTAL);

    __half *xh, *yh, *wq, *wp;
    cudaGetSymbolAddress((void**)&xh, g_xh);
    cudaGetSymbolAddress((void**)&yh, g_yh);
    cudaGetSymbolAddress((void**)&wq, g_wqkvT);
    cudaGetSymbolAddress((void**)&wp, g_wprojT);

    // fused prep (convert x + transpose both weights)
    prep_kernel<<<PREP_BLOCKS, 256>>>(x, w_qkv, w_proj);

    // QKV GEMM (1-term) with fused q-scale + scatter
    mma_gemm_kernel<<<dim3(N_QKV / 128, M_ / 128), 256, SM_GEMM_TOTAL>>>(
        xh, wq, nullptr, 0);

    // tensor-core causal flash attention (all fp16 operands)
    attn_mma_kernel<<<dim3(B_ * H_, T_ / 128), 256, AS_TOTAL>>>();

    // output projection GEMM (1-term)
    mma_gemm_kernel<<<dim3(C_ / 128, M_ / 128), 256, SM_GEMM_TOTAL>>>(
        yh, wp, out, 1);
}